// round 12
// baseline (speedup 1.0000x reference)
#include <cuda_runtime.h>
#include <cuda_fp16.h>
#include <mma.h>
#include <math.h>

using namespace nvcuda;

#define N_ATOMS 100000
#define N_EDGES 3200000
#define N_MOL   2000
#define HID     64
#define NGAUSS  50
#define NLAYERS 3
#define TBL_T   512
#define TBL2_BYTES (TBL_T * HID * 4)       /* 128 KB: (a, delta/64) interleaved */
#define DMAX    8.6603f                    /* >= 5*sqrt(3) */
#define TBL_SCALE ((float)(TBL_T-1) / DMAX)
#define TBL_SCALE64 (TBL_SCALE * 64.0f)
#define TI6_MAX ((TBL_T - 2) * 64 + 63)    /* 32703 */
#define LOG2F_  0.69314718055994530942f
#define PI_OVER_CUTOFF 0.31415926535897932385f
#define SCAN_BLK 98
#define AGG_BLOCKS 148
#define TB_TPB  16

#define WPREP_BLK 48
#define POS_BLK   ((N_ATOMS + 255) / 256)
#define TBL_BLK   (NLAYERS * (TBL_T / TB_TPB))
#define HIST_BLK  ((N_EDGES + 255) / 256)

#define PACK_BLK  ((NLAYERS * TBL_T * 32 + 255) / 256)
#define DX_BLK    ((N_ATOMS + 127) / 128)
#define SCANC_BLK ((N_ATOMS + 255) / 256)

#define LDA 72
#define LDC 68
#define SM_A_OFF  0
#define SM_B_OFF  (128 * LDA * 2)
#define SM_C_OFF  (SM_B_OFF + 64 * LDA * 2)
#define SM_TOTAL  (SM_C_OFF + 128 * LDC * 4)

/* ------------------------- scratch (no allocs allowed) ------------------ */
__device__ int                g_hist[N_ATOMS];
__device__ int                g_row[N_ATOMS + 1];
__device__ int                g_cur[N_ATOMS];
__device__ int                g_part[128];
__device__ int                g_done;
__device__ int                g_flag;
__device__ unsigned int       g_edata[N_EDGES];      /* s:17 | ti:9 | f6:6 */
__device__ float4             g_pos4[N_ATOMS];
__device__ __align__(16)  __half g_traw[NLAYERS * TBL_T * HID];
__device__ __align__(16)  __half g_tbl2[NLAYERS * TBL_T * HID * 2];
__device__ float              g_h[(size_t)N_ATOMS * HID];
__device__ __align__(128) __half g_x[(size_t)N_ATOMS * HID];
__device__ __align__(128) __half g_aggh[(size_t)N_ATOMS * HID];
__device__ float              g_molsum[N_MOL];
__device__ __align__(16) __half g_cf1h[NLAYERS * HID * HID];
__device__ __align__(16) __half g_cf2h[NLAYERS * HID * HID];
__device__ __align__(16) __half g_inth[NLAYERS * HID * HID];

__device__ __forceinline__ float ssp(float v) {
    return fmaxf(v, 0.0f) + log1pf(expf(-fabsf(v))) - LOG2F_;
}

/* --------------- wmma 128x64x64 tile helpers ----------------------------- */
__device__ __forceinline__ void wmma_gemm(const __half* sA, const __half* sB, float* sC) {
    int w = threadIdx.x >> 5;
    wmma::fragment<wmma::accumulator, 16, 16, 16, float> c[4];
#pragma unroll
    for (int n = 0; n < 4; n++) wmma::fill_fragment(c[n], 0.0f);
#pragma unroll
    for (int k = 0; k < 4; k++) {
        wmma::fragment<wmma::matrix_a, 16, 16, 16, __half, wmma::row_major> a;
        wmma::load_matrix_sync(a, sA + (w * 16) * LDA + k * 16, LDA);
#pragma unroll
        for (int n = 0; n < 4; n++) {
            wmma::fragment<wmma::matrix_b, 16, 16, 16, __half, wmma::row_major> b;
            wmma::load_matrix_sync(b, sB + (k * 16) * LDA + n * 16, LDA);
            wmma::mma_sync(c[n], a, b, c[n]);
        }
    }
#pragma unroll
    for (int n = 0; n < 4; n++)
        wmma::store_matrix_sync(sC + (w * 16) * LDC + n * 16, c[n], LDC, wmma::mem_row_major);
}

__device__ __forceinline__ void load_B(__half* sB, const __half* W, int tid) {
    for (int i = tid; i < 64 * 32; i += 256) {
        int row = i >> 5, c2 = i & 31;
        *(unsigned int*)&sB[row * LDA + c2 * 2] = ((const unsigned int*)W)[row * 32 + c2];
    }
}

/* =========== K1: wprep + pos4 repack + table + hist (fused) ============== */
__global__ void __launch_bounds__(256) k1_prep_table_hist(
        const float* __restrict__ cf1, const float* __restrict__ cf2,
        const float* __restrict__ intw,
        const float* __restrict__ w1, const float* __restrict__ b1,
        const float* __restrict__ w2, const float* __restrict__ b2,
        const int* __restrict__ ei, const float* __restrict__ pos) {
    int bid = blockIdx.x;
    int tid = threadIdx.x;

    if (bid < WPREP_BLK) {
        int i = bid * 256 + tid;
        if (i < NLAYERS * HID * HID) {
            g_cf1h[i] = __float2half_rn(cf1[i]);
            g_cf2h[i] = __float2half_rn(cf2[i]);
            g_inth[i] = __float2half_rn(intw[i]);
        }
        return;
    }
    if (bid < WPREP_BLK + POS_BLK) {
        int i = (bid - WPREP_BLK) * 256 + tid;
        if (i < N_ATOMS)
            g_pos4[i] = make_float4(pos[3 * i], pos[3 * i + 1], pos[3 * i + 2], 0.0f);
        return;
    }
    if (bid < WPREP_BLK + POS_BLK + TBL_BLK) {
        __shared__ float W1s[NGAUSS][HID];
        __shared__ float W2s[HID][HID];
        __shared__ float rbfs[TB_TPB][NGAUSS];
        __shared__ float tmps[TB_TPB][HID];
        int tb = bid - WPREP_BLK - POS_BLK;
        int l = tb / (TBL_T / TB_TPB);
        int tbase = (tb % (TBL_T / TB_TPB)) * TB_TPB;

        for (int i = tid; i < NGAUSS * HID; i += 256)
            W1s[i / HID][i % HID] = w1[(size_t)l * NGAUSS * HID + i];
        for (int i = tid; i < HID * HID; i += 256)
            W2s[i >> 6][i & 63] = w2[(size_t)l * HID * HID + i];
        for (int i = tid; i < TB_TPB * NGAUSS; i += 256) {
            int tt = i / NGAUSS, k = i % NGAUSS;
            float d = (float)(tbase + tt) * (DMAX / (float)(TBL_T - 1));
            float off = (float)k * (10.0f / 49.0f);
            float u = d - off;
            const float coeff = -0.5f * (49.0f / 10.0f) * (49.0f / 10.0f);
            rbfs[tt][k] = expf(coeff * u * u);
        }
        __syncthreads();

        for (int i = tid; i < TB_TPB * HID; i += 256) {
            int tt = i >> 6, j = i & 63;
            float acc = b1[l * HID + j];
#pragma unroll
            for (int k = 0; k < NGAUSS; k++) acc = fmaf(rbfs[tt][k], W1s[k][j], acc);
            tmps[tt][j] = ssp(acc);
        }
        __syncthreads();

        for (int i = tid; i < TB_TPB * HID; i += 256) {
            int tt = i >> 6, j = i & 63;
            float acc = b2[l * HID + j];
#pragma unroll
            for (int k = 0; k < HID; k++) acc = fmaf(tmps[tt][k], W2s[k][j], acc);
            float d = (float)(tbase + tt) * (DMAX / (float)(TBL_T - 1));
            float C = 0.5f * (cosf(d * PI_OVER_CUTOFF) + 1.0f);
            g_traw[((size_t)l * TBL_T + tbase + tt) * HID + j] = __float2half_rn(acc * C);
        }
        return;
    }
    int e = (bid - WPREP_BLK - POS_BLK - TBL_BLK) * 256 + tid;
    if (e < N_EDGES) atomicAdd(&g_hist[ei[N_EDGES + e]], 1);
}

/* ====== K2: scanA(+B last block) + pack + dense_x + scanC(spin) ========== */
__global__ void __launch_bounds__(256) k2_scan_pack_densex(const int* __restrict__ z,
                                                           const float* __restrict__ emb) {
    int bid = blockIdx.x;
    int tid = threadIdx.x;

    if (bid < SCAN_BLK) {
        __shared__ int wsum[8];
        __shared__ int s_last;
        int lane = tid & 31, wid = tid >> 5;
        int idx = bid * 1024 + tid * 4;

        int v0 = (idx + 0 < N_ATOMS) ? g_hist[idx + 0] : 0;
        int v1 = (idx + 1 < N_ATOMS) ? g_hist[idx + 1] : 0;
        int v2 = (idx + 2 < N_ATOMS) ? g_hist[idx + 2] : 0;
        int v3 = (idx + 3 < N_ATOMS) ? g_hist[idx + 3] : 0;
        if (idx + 0 < N_ATOMS) g_hist[idx + 0] = 0;
        if (idx + 1 < N_ATOMS) g_hist[idx + 1] = 0;
        if (idx + 2 < N_ATOMS) g_hist[idx + 2] = 0;
        if (idx + 3 < N_ATOMS) g_hist[idx + 3] = 0;

        int s = v0 + v1 + v2 + v3;
        int si = s;
#pragma unroll
        for (int o = 1; o < 32; o <<= 1) {
            int u = __shfl_up_sync(0xffffffffu, si, o);
            if (lane >= o) si += u;
        }
        if (lane == 31) wsum[wid] = si;
        __syncthreads();
        if (wid == 0 && lane < 8) {
            int w = wsum[lane];
#pragma unroll
            for (int o = 1; o < 8; o <<= 1) {
                int u = __shfl_up_sync(0x000000ffu, w, o);
                if (lane >= o) w += u;
            }
            wsum[lane] = w;
        }
        __syncthreads();
        int off = ((wid > 0) ? wsum[wid - 1] : 0) + (si - s);
        if (idx + 0 < N_ATOMS) g_row[idx + 0] = off;
        if (idx + 1 < N_ATOMS) g_row[idx + 1] = off + v0;
        if (idx + 2 < N_ATOMS) g_row[idx + 2] = off + v0 + v1;
        if (idx + 3 < N_ATOMS) g_row[idx + 3] = off + v0 + v1 + v2;
        if (tid == 0) g_part[bid] = wsum[7];

        __threadfence();
        if (tid == 0) s_last = (atomicAdd(&g_done, 1) == SCAN_BLK - 1);
        __syncthreads();
        if (s_last) {
            __threadfence();
            if (tid < 32) {
                int lane2 = tid;
                int i = lane2 * 4;
                int u0 = (i + 0 < SCAN_BLK) ? g_part[i + 0] : 0;
                int u1 = (i + 1 < SCAN_BLK) ? g_part[i + 1] : 0;
                int u2 = (i + 2 < SCAN_BLK) ? g_part[i + 2] : 0;
                int u3 = (i + 3 < SCAN_BLK) ? g_part[i + 3] : 0;
                int ss = u0 + u1 + u2 + u3;
                int ssi = ss;
#pragma unroll
                for (int o = 1; o < 32; o <<= 1) {
                    int u = __shfl_up_sync(0xffffffffu, ssi, o);
                    if (lane2 >= o) ssi += u;
                }
                int excl = ssi - ss;
                if (i + 0 < SCAN_BLK) g_part[i + 0] = excl;
                if (i + 1 < SCAN_BLK) g_part[i + 1] = excl + u0;
                if (i + 2 < SCAN_BLK) g_part[i + 2] = excl + u0 + u1;
                if (i + 3 < SCAN_BLK) g_part[i + 3] = excl + u0 + u1 + u2;
                if (lane2 == 31) g_row[N_ATOMS] = ssi;
                __syncwarp();
                if (lane2 == 0) {
                    g_done = 0;
                    __threadfence();
                    g_flag = 1;
                }
            }
        }
        return;
    }
    if (bid < SCAN_BLK + PACK_BLK) {
        /* pack raw -> interleaved (a, delta/64) 256B rows */
        int i = (bid - SCAN_BLK) * 256 + tid;
        if (i >= NLAYERS * TBL_T * 32) return;
        int c2 = i & 31;
        int t  = (i >> 5) & (TBL_T - 1);
        int l  = i / (TBL_T * 32);
        const __half2* raw = (const __half2*)g_traw;
        __half2 a = raw[((size_t)l * TBL_T + t) * 32 + c2];
        int tn = (t + 1 < TBL_T) ? t + 1 : t;
        __half2 b = raw[((size_t)l * TBL_T + tn) * 32 + c2];
        __half2 d = __hmul2(__hsub2(b, a), __float2half2_rn(1.0f / 64.0f));
        __half2* dst = (__half2*)g_tbl2;
        dst[(((size_t)l * TBL_T + t) * 32 + c2) * 2 + 0] = a;
        dst[(((size_t)l * TBL_T + t) * 32 + c2) * 2 + 1] = d;
        return;
    }
    if (bid < SCAN_BLK + PACK_BLK + DX_BLK) {
        extern __shared__ char sm[];
        __half* sA = (__half*)(sm + SM_A_OFF);
        __half* sB = (__half*)(sm + SM_B_OFF);
        float*  sC = (float*)(sm + SM_C_OFF);
        size_t r0 = (size_t)(bid - SCAN_BLK - PACK_BLK) * 128;

        for (int i = tid; i < 128 * 64; i += 256) {
            int row = i >> 6, col = i & 63;
            size_t gr = r0 + row;
            float v = 0.0f;
            if (gr < N_ATOMS) {
                v = emb[(size_t)z[gr] * HID + col];
                g_h[gr * HID + col] = v;
            }
            sA[row * LDA + col] = __float2half_rn(v);
        }
        load_B(sB, g_cf1h, tid);
        __syncthreads();
        wmma_gemm(sA, sB, sC);
        __syncthreads();
        for (int i = tid; i < 128 * 32; i += 256) {
            int row = i >> 5, c2 = i & 31;
            size_t gr = r0 + row;
            if (gr < N_ATOMS) {
                __half2 hv = __floats2half2_rn(sC[row * LDC + c2 * 2], sC[row * LDC + c2 * 2 + 1]);
                *(__half2*)(g_x + gr * HID + c2 * 2) = hv;
            }
        }
        return;
    }
    if (tid == 0) {
        while (!*((volatile int*)&g_flag)) __nanosleep(64);
    }
    __syncthreads();
    __threadfence();
    int i = (bid - SCAN_BLK - PACK_BLK - DX_BLK) * 256 + tid;
    if (i >= N_ATOMS) return;
    int v = g_row[i] + g_part[i >> 10];
    g_row[i] = v;
    g_cur[i] = v;
}

/* =================== K3: scatter (32-bit records, 6-bit f) =============== */
__global__ void scatter_kernel(const int* __restrict__ ei) {
    int e = blockIdx.x * blockDim.x + threadIdx.x;
    if (e == 0) g_flag = 0;
    if (e >= N_EDGES) return;
    int s = ei[e];
    int t = ei[N_EDGES + e];
    float4 ps = g_pos4[s];
    float4 pt = g_pos4[t];
    float dx = ps.x - pt.x, dy = ps.y - pt.y, dz = ps.z - pt.z;
    float d = sqrtf(dx * dx + dy * dy + dz * dz);
    unsigned ti6 = min((unsigned)(d * TBL_SCALE64), (unsigned)TI6_MAX);
    int p = atomicAdd(&g_cur[t], 1);
    g_edata[p] = ((unsigned)s << 15) | ti6;
}

/* ====== K4: aggregate — quarter-warp per node (PROFILED SLOT) ============ */
__global__ void __launch_bounds__(1024, 1) aggregate_kernel(int layer) {
    extern __shared__ __align__(16) char s_raw[];
    {
        const uint4* src = (const uint4*)(g_tbl2 + (size_t)layer * TBL_T * HID * 2);
        uint4* dst = (uint4*)s_raw;
        for (int i = threadIdx.x; i < TBL2_BYTES / 16; i += 1024) dst[i] = src[i];
    }
    __syncthreads();

    int lane = threadIdx.x & 31;
    int wib  = threadIdx.x >> 5;
    int q    = lane >> 3;              /* node slot 0..3 within warp       */
    int l8   = lane & 7;               /* lane in group: ch 4l8..+3, 32+4l8..+3 */
    unsigned xoff = (unsigned)l8 << 3;  /* 8B into x row   */
    unsigned toff = (unsigned)l8 << 4;  /* 16B into table row */
    const char* xg = (const char*)g_x;

    for (int nodeb = blockIdx.x * 128 + wib * 4; nodeb < N_ATOMS; nodeb += gridDim.x * 128) {
        int node = nodeb + q;
        int beg = 0, end = 0;
        if (node < N_ATOMS) { beg = g_row[node]; end = g_row[node + 1]; }

        int nb = (end - beg + 7) >> 3;
        nb = max(nb, __shfl_xor_sync(0xffffffffu, nb, 8));
        nb = max(nb, __shfl_xor_sync(0xffffffffu, nb, 16));

        __half2 a0 = __half2half2(__ushort_as_half(0));
        __half2 a1 = a0, a2 = a0, a3 = a0;
        float f0 = 0.f, f1 = 0.f, f2a = 0.f, f3 = 0.f,
              f4 = 0.f, f5 = 0.f, f6 = 0.f, f7 = 0.f;
        int it = 0;

        for (int b = 0; b < nb; b++) {
            int base = beg + (b << 3);
            int cnt = end - base;                      /* valid: 0..cnt-1  */
            unsigned pk = (l8 < cnt) ? __ldcs(&g_edata[base + l8]) : 0u;
            int cmax = min(cnt, 8);
            cmax = max(cmax, __shfl_xor_sync(0xffffffffu, cmax, 8));
            cmax = max(cmax, __shfl_xor_sync(0xffffffffu, cmax, 16));

            for (int j = 0; j < cmax; j++) {
                unsigned p = __shfl_sync(0xffffffffu, pk, j, 8);
                uint2 x0 = make_uint2(0u, 0u), x1 = make_uint2(0u, 0u);
                if (j < cnt) {
                    const char* xp = xg + ((size_t)(p >> 15) << 7);
                    x0 = *(const uint2*)(xp + xoff);
                    x1 = *(const uint2*)(xp + 64 + xoff);
                }
                const char* trow = s_raw + ((p & 0x7FC0u) << 2);
                uint4 t0 = *(const uint4*)(trow + toff);
                uint4 t1 = *(const uint4*)(trow + 128 + toff);
                __half2 fr = __half2half2(__ushort2half_rn((unsigned short)(p & 63u)));

                a0 = __hadd2(a0, __hmul2(__hfma2(fr, *(__half2*)&t0.y, *(__half2*)&t0.x), *(__half2*)&x0.x));
                a1 = __hadd2(a1, __hmul2(__hfma2(fr, *(__half2*)&t0.w, *(__half2*)&t0.z), *(__half2*)&x0.y));
                a2 = __hadd2(a2, __hmul2(__hfma2(fr, *(__half2*)&t1.y, *(__half2*)&t1.x), *(__half2*)&x1.x));
                a3 = __hadd2(a3, __hmul2(__hfma2(fr, *(__half2*)&t1.w, *(__half2*)&t1.z), *(__half2*)&x1.y));

                if ((++it & 3) == 0) {
                    float2 v;
                    v = __half22float2(a0); f0 += v.x; f1 += v.y;
                    v = __half22float2(a1); f2a += v.x; f3 += v.y;
                    v = __half22float2(a2); f4 += v.x; f5 += v.y;
                    v = __half22float2(a3); f6 += v.x; f7 += v.y;
                    a0 = __half2half2(__ushort_as_half(0));
                    a1 = a0; a2 = a0; a3 = a0;
                }
            }
        }
        {
            float2 v;
            v = __half22float2(a0); f0 += v.x; f1 += v.y;
            v = __half22float2(a1); f2a += v.x; f3 += v.y;
            v = __half22float2(a2); f4 += v.x; f5 += v.y;
            v = __half22float2(a3); f6 += v.x; f7 += v.y;
        }

        if (node < N_ATOMS) {
            __half2 h0 = __floats2half2_rn(f0, f1);
            __half2 h1 = __floats2half2_rn(f2a, f3);
            __half2 h2 = __floats2half2_rn(f4, f5);
            __half2 h3 = __floats2half2_rn(f6, f7);
            uint2 s0, s1;
            s0.x = *(unsigned*)&h0; s0.y = *(unsigned*)&h1;
            s1.x = *(unsigned*)&h2; s1.y = *(unsigned*)&h3;
            char* dst = (char*)g_aggh + (size_t)node * 128;
            *(uint2*)(dst + xoff)      = s0;
            *(uint2*)(dst + 64 + xoff) = s1;
        }
    }
}

/* --- h += ssp(agg@W1+b1)@W2+b2 ; x = h_new@W3 (all tensor-core) ---------- */
__global__ void __launch_bounds__(256) dense_post_w(int l, int fuse_next,
                                                    const float* __restrict__ b1,
                                                    const float* __restrict__ b2) {
    extern __shared__ char sm[];
    __half* sA = (__half*)(sm + SM_A_OFF);
    __half* sB = (__half*)(sm + SM_B_OFF);
    float*  sC = (float*)(sm + SM_C_OFF);
    int tid = threadIdx.x;
    size_t r0 = (size_t)blockIdx.x * 128;

    const __half* W1 = g_cf2h + (size_t)l * HID * HID;
    const __half* W2 = g_inth + (size_t)l * HID * HID;
    const __half* W3 = g_cf1h + (size_t)(l + 1 < NLAYERS ? l + 1 : 0) * HID * HID;

    for (int i = tid; i < 128 * 32; i += 256) {
        int row = i >> 5, c2 = i & 31;
        unsigned int v = 0;
        if (r0 + row < N_ATOMS)
            v = ((const unsigned int*)g_aggh)[(r0 + row) * 32 + c2];
        *(unsigned int*)&sA[row * LDA + c2 * 2] = v;
    }
    load_B(sB, W1, tid);
    __syncthreads();
    wmma_gemm(sA, sB, sC);
    __syncthreads();

    for (int i = tid; i < 128 * 64; i += 256) {
        int row = i >> 6, col = i & 63;
        float v = ssp(sC[row * LDC + col] + __ldg(&b1[col]));
        sA[row * LDA + col] = __float2half_rn(v);
    }
    load_B(sB, W2, tid);
    __syncthreads();
    wmma_gemm(sA, sB, sC);
    __syncthreads();

    for (int i = tid; i < 128 * 64; i += 256) {
        int row = i >> 6, col = i & 63;
        size_t gr = r0 + row;
        float v = 0.0f;
        if (gr < N_ATOMS) {
            v = g_h[gr * HID + col] + sC[row * LDC + col] + __ldg(&b2[col]);
            g_h[gr * HID + col] = v;
        }
        sA[row * LDA + col] = __float2half_rn(v);
    }
    if (!fuse_next) return;

    load_B(sB, W3, tid);
    __syncthreads();
    wmma_gemm(sA, sB, sC);
    __syncthreads();
    for (int i = tid; i < 128 * 32; i += 256) {
        int row = i >> 5, c2 = i & 31;
        size_t gr = r0 + row;
        if (gr < N_ATOMS) {
            __half2 hv = __floats2half2_rn(sC[row * LDC + c2 * 2], sC[row * LDC + c2 * 2 + 1]);
            *(__half2*)(g_x + gr * HID + c2 * 2) = hv;
        }
    }
}

/* --------------- readout: per-atom MLP (64->32->1) + molecule sum -------- */
__global__ void readout_kernel(const int* __restrict__ batch,
                               const float* __restrict__ w1, const float* __restrict__ b1,
                               const float* __restrict__ w2, const float* __restrict__ b2) {
    int warp = (blockIdx.x * blockDim.x + threadIdx.x) >> 5;
    int lane = threadIdx.x & 31;
    if (warp >= N_ATOMS) return;

    float h0 = g_h[(size_t)warp * HID + lane];
    float h1 = g_h[(size_t)warp * HID + 32 + lane];

    float acc = b1[lane];
#pragma unroll
    for (int k = 0; k < 32; k++) {
        float hk = __shfl_sync(0xffffffffu, h0, k);
        acc = fmaf(hk, w1[k * 32 + lane], acc);
    }
#pragma unroll
    for (int k = 0; k < 32; k++) {
        float hk = __shfl_sync(0xffffffffu, h1, k);
        acc = fmaf(hk, w1[(32 + k) * 32 + lane], acc);
    }
    float t = ssp(acc) * w2[lane];
#pragma unroll
    for (int o = 16; o > 0; o >>= 1) t += __shfl_xor_sync(0xffffffffu, t, o);
    if (lane == 0) atomicAdd(&g_molsum[batch[warp]], t + b2[0]);
}

/* ------- out[g] = molsum[g]*fin_w + fin_b ; self-restore molsum ---------- */
__global__ void final_kernel(const float* __restrict__ fw, const float* __restrict__ fb,
                             float* __restrict__ out) {
    int g = blockIdx.x * blockDim.x + threadIdx.x;
    if (g < N_MOL) {
        float v = g_molsum[g];
        out[g] = v * fw[0] + fb[0];
        g_molsum[g] = 0.0f;
    }
}

/* ========================================================================= */
extern "C" void kernel_launch(void* const* d_in, const int* in_sizes, int n_in,
                              void* d_out, int out_size) {
    const int*   z      = (const int*)d_in[0];
    const float* pos    = (const float*)d_in[1];
    const int*   batch  = (const int*)d_in[2];
    const int*   ei     = (const int*)d_in[3];
    const float* emb    = (const float*)d_in[4];
    const float* out_w1 = (const float*)d_in[5];
    const float* out_b1 = (const float*)d_in[6];
    const float* out_w2 = (const float*)d_in[7];
    const float* out_b2 = (const float*)d_in[8];
    const float* fin_w  = (const float*)d_in[9];
    const float* fin_b  = (const float*)d_in[10];
    const float* mlp_w1 = (const float*)d_in[11];
    const float* mlp_b1 = (const float*)d_in[12];
    const float* mlp_w2 = (const float*)d_in[13];
    const float* mlp_b2 = (const float*)d_in[14];
    const float* cf1    = (const float*)d_in[15];
    const float* cf2    = (const float*)d_in[16];
    const float* cf2b   = (const float*)d_in[17];
    const float* intw   = (const float*)d_in[18];
    const float* intb   = (const float*)d_in[19];

    (void)in_sizes; (void)n_in; (void)out_size;

    cudaFuncSetAttribute(aggregate_kernel,
                         cudaFuncAttributeMaxDynamicSharedMemorySize, TBL2_BYTES);
    cudaFuncSetAttribute(k2_scan_pack_densex,
                         cudaFuncAttributeMaxDynamicSharedMemorySize, SM_TOTAL);
    cudaFuncSetAttribute(dense_post_w,
                         cudaFuncAttributeMaxDynamicSharedMemorySize, SM_TOTAL);

    k1_prep_table_hist<<<WPREP_BLK + POS_BLK + TBL_BLK + HIST_BLK, 256>>>(
        cf1, cf2, intw, mlp_w1, mlp_b1, mlp_w2, mlp_b2, ei, pos);
    k2_scan_pack_densex<<<SCAN_BLK + PACK_BLK + DX_BLK + SCANC_BLK, 256, SM_TOTAL>>>(z, emb);
    scatter_kernel<<<(N_EDGES + 255) / 256, 256>>>(ei);

    for (int l = 0; l < NLAYERS; l++) {
        aggregate_kernel<<<AGG_BLOCKS, 1024, TBL2_BYTES>>>(l);
        dense_post_w<<<DX_BLK, 256, SM_TOTAL>>>(l, (l + 1 < NLAYERS),
                                                cf2b + (size_t)l * HID,
                                                intb + (size_t)l * HID);
    }

    int warp_blocks = (N_ATOMS * 32 + 255) / 256;
    readout_kernel<<<warp_blocks, 256>>>(batch, out_w1, out_b1, out_w2, out_b2);
    final_kernel<<<(N_MOL + 255) / 256, 256>>>(fin_w, fin_b, (float*)d_out);
}

// round 13
// speedup vs baseline: 1.0655x; 1.0655x over previous
#include <cuda_runtime.h>
#include <cuda_fp16.h>
#include <mma.h>
#include <math.h>

using namespace nvcuda;

#define N_ATOMS 100000
#define N_EDGES 3200000
#define N_MOL   2000
#define HID     64
#define NGAUSS  50
#define NLAYERS 3
#define TBL_T   512
#define TBL2_BYTES (TBL_T * HID * 4)       /* 128 KB: (a, delta/64) interleaved */
#define DMAX    8.6603f                    /* >= 5*sqrt(3) */
#define TBL_SCALE ((float)(TBL_T-1) / DMAX)
#define TBL_SCALE64 (TBL_SCALE * 64.0f)
#define TI6_MAX ((TBL_T - 2) * 64 + 63)    /* 32703 */
#define LOG2F_  0.69314718055994530942f
#define PI_OVER_CUTOFF 0.31415926535897932385f
#define SCAN_BLK 98
#define AGG_BLOCKS 148
#define TB_TPB  16

#define WPREP_BLK 48
#define POS_BLK   ((N_ATOMS + 255) / 256)
#define TBL_BLK   (NLAYERS * (TBL_T / TB_TPB))
#define HIST_BLK  ((N_EDGES + 255) / 256)

#define PACK_BLK  ((NLAYERS * TBL_T * 32 + 255) / 256)
#define DX_BLK    ((N_ATOMS + 127) / 128)
#define SCANC_BLK ((N_ATOMS + 255) / 256)

#define LDA 72
#define LDC 68
#define SM_A_OFF  0
#define SM_B_OFF  (128 * LDA * 2)
#define SM_C_OFF  (SM_B_OFF + 64 * LDA * 2)
#define SM_TOTAL  (SM_C_OFF + 128 * LDC * 4)

/* ------------------------- scratch (no allocs allowed) ------------------ */
__device__ int                g_hist[N_ATOMS];
__device__ int                g_row[N_ATOMS + 1];
__device__ int                g_cur[N_ATOMS];
__device__ int                g_part[128];
__device__ int                g_done;
__device__ int                g_flag;
__device__ unsigned int       g_edata[N_EDGES];      /* s:17 | ti:9 | f6:6 */
__device__ float4             g_pos4[N_ATOMS];
__device__ __align__(16)  __half g_traw[NLAYERS * TBL_T * HID];
__device__ __align__(16)  __half g_tbl2[NLAYERS * TBL_T * HID * 2];
__device__ float              g_h[(size_t)N_ATOMS * HID];
__device__ __align__(128) __half g_x[(size_t)N_ATOMS * HID];
__device__ __align__(128) __half g_aggh[(size_t)N_ATOMS * HID];
__device__ float              g_molsum[N_MOL];
__device__ __align__(16) __half g_cf1h[NLAYERS * HID * HID];
__device__ __align__(16) __half g_cf2h[NLAYERS * HID * HID];
__device__ __align__(16) __half g_inth[NLAYERS * HID * HID];

__device__ __forceinline__ float ssp(float v) {
    return fmaxf(v, 0.0f) + log1pf(expf(-fabsf(v))) - LOG2F_;
}

/* --------------- wmma 128x64x64 tile helpers ----------------------------- */
__device__ __forceinline__ void wmma_gemm(const __half* sA, const __half* sB, float* sC) {
    int w = threadIdx.x >> 5;
    wmma::fragment<wmma::accumulator, 16, 16, 16, float> c[4];
#pragma unroll
    for (int n = 0; n < 4; n++) wmma::fill_fragment(c[n], 0.0f);
#pragma unroll
    for (int k = 0; k < 4; k++) {
        wmma::fragment<wmma::matrix_a, 16, 16, 16, __half, wmma::row_major> a;
        wmma::load_matrix_sync(a, sA + (w * 16) * LDA + k * 16, LDA);
#pragma unroll
        for (int n = 0; n < 4; n++) {
            wmma::fragment<wmma::matrix_b, 16, 16, 16, __half, wmma::row_major> b;
            wmma::load_matrix_sync(b, sB + (k * 16) * LDA + n * 16, LDA);
            wmma::mma_sync(c[n], a, b, c[n]);
        }
    }
#pragma unroll
    for (int n = 0; n < 4; n++)
        wmma::store_matrix_sync(sC + (w * 16) * LDC + n * 16, c[n], LDC, wmma::mem_row_major);
}

__device__ __forceinline__ void load_B(__half* sB, const __half* W, int tid) {
    for (int i = tid; i < 64 * 32; i += 256) {
        int row = i >> 5, c2 = i & 31;
        *(unsigned int*)&sB[row * LDA + c2 * 2] = ((const unsigned int*)W)[row * 32 + c2];
    }
}

/* =========== K1: wprep + pos4 repack + table + hist (fused) ============== */
__global__ void __launch_bounds__(256) k1_prep_table_hist(
        const float* __restrict__ cf1, const float* __restrict__ cf2,
        const float* __restrict__ intw,
        const float* __restrict__ w1, const float* __restrict__ b1,
        const float* __restrict__ w2, const float* __restrict__ b2,
        const int* __restrict__ ei, const float* __restrict__ pos) {
    int bid = blockIdx.x;
    int tid = threadIdx.x;

    if (bid < WPREP_BLK) {
        int i = bid * 256 + tid;
        if (i < NLAYERS * HID * HID) {
            g_cf1h[i] = __float2half_rn(cf1[i]);
            g_cf2h[i] = __float2half_rn(cf2[i]);
            g_inth[i] = __float2half_rn(intw[i]);
        }
        return;
    }
    if (bid < WPREP_BLK + POS_BLK) {
        int i = (bid - WPREP_BLK) * 256 + tid;
        if (i < N_ATOMS)
            g_pos4[i] = make_float4(pos[3 * i], pos[3 * i + 1], pos[3 * i + 2], 0.0f);
        return;
    }
    if (bid < WPREP_BLK + POS_BLK + TBL_BLK) {
        __shared__ float W1s[NGAUSS][HID];
        __shared__ float W2s[HID][HID];
        __shared__ float rbfs[TB_TPB][NGAUSS];
        __shared__ float tmps[TB_TPB][HID];
        int tb = bid - WPREP_BLK - POS_BLK;
        int l = tb / (TBL_T / TB_TPB);
        int tbase = (tb % (TBL_T / TB_TPB)) * TB_TPB;

        for (int i = tid; i < NGAUSS * HID; i += 256)
            W1s[i / HID][i % HID] = w1[(size_t)l * NGAUSS * HID + i];
        for (int i = tid; i < HID * HID; i += 256)
            W2s[i >> 6][i & 63] = w2[(size_t)l * HID * HID + i];
        for (int i = tid; i < TB_TPB * NGAUSS; i += 256) {
            int tt = i / NGAUSS, k = i % NGAUSS;
            float d = (float)(tbase + tt) * (DMAX / (float)(TBL_T - 1));
            float off = (float)k * (10.0f / 49.0f);
            float u = d - off;
            const float coeff = -0.5f * (49.0f / 10.0f) * (49.0f / 10.0f);
            rbfs[tt][k] = expf(coeff * u * u);
        }
        __syncthreads();

        for (int i = tid; i < TB_TPB * HID; i += 256) {
            int tt = i >> 6, j = i & 63;
            float acc = b1[l * HID + j];
#pragma unroll
            for (int k = 0; k < NGAUSS; k++) acc = fmaf(rbfs[tt][k], W1s[k][j], acc);
            tmps[tt][j] = ssp(acc);
        }
        __syncthreads();

        for (int i = tid; i < TB_TPB * HID; i += 256) {
            int tt = i >> 6, j = i & 63;
            float acc = b2[l * HID + j];
#pragma unroll
            for (int k = 0; k < HID; k++) acc = fmaf(tmps[tt][k], W2s[k][j], acc);
            float d = (float)(tbase + tt) * (DMAX / (float)(TBL_T - 1));
            float C = 0.5f * (cosf(d * PI_OVER_CUTOFF) + 1.0f);
            g_traw[((size_t)l * TBL_T + tbase + tt) * HID + j] = __float2half_rn(acc * C);
        }
        return;
    }
    int e = (bid - WPREP_BLK - POS_BLK - TBL_BLK) * 256 + tid;
    if (e < N_EDGES) atomicAdd(&g_hist[ei[N_EDGES + e]], 1);
}

/* ====== K2: scanA(+B last block) + pack + dense_x + scanC(spin) ========== */
__global__ void __launch_bounds__(256) k2_scan_pack_densex(const int* __restrict__ z,
                                                           const float* __restrict__ emb) {
    int bid = blockIdx.x;
    int tid = threadIdx.x;

    if (bid < SCAN_BLK) {
        __shared__ int wsum[8];
        __shared__ int s_last;
        int lane = tid & 31, wid = tid >> 5;
        int idx = bid * 1024 + tid * 4;

        int v0 = (idx + 0 < N_ATOMS) ? g_hist[idx + 0] : 0;
        int v1 = (idx + 1 < N_ATOMS) ? g_hist[idx + 1] : 0;
        int v2 = (idx + 2 < N_ATOMS) ? g_hist[idx + 2] : 0;
        int v3 = (idx + 3 < N_ATOMS) ? g_hist[idx + 3] : 0;
        if (idx + 0 < N_ATOMS) g_hist[idx + 0] = 0;
        if (idx + 1 < N_ATOMS) g_hist[idx + 1] = 0;
        if (idx + 2 < N_ATOMS) g_hist[idx + 2] = 0;
        if (idx + 3 < N_ATOMS) g_hist[idx + 3] = 0;

        int s = v0 + v1 + v2 + v3;
        int si = s;
#pragma unroll
        for (int o = 1; o < 32; o <<= 1) {
            int u = __shfl_up_sync(0xffffffffu, si, o);
            if (lane >= o) si += u;
        }
        if (lane == 31) wsum[wid] = si;
        __syncthreads();
        if (wid == 0 && lane < 8) {
            int w = wsum[lane];
#pragma unroll
            for (int o = 1; o < 8; o <<= 1) {
                int u = __shfl_up_sync(0x000000ffu, w, o);
                if (lane >= o) w += u;
            }
            wsum[lane] = w;
        }
        __syncthreads();
        int off = ((wid > 0) ? wsum[wid - 1] : 0) + (si - s);
        if (idx + 0 < N_ATOMS) g_row[idx + 0] = off;
        if (idx + 1 < N_ATOMS) g_row[idx + 1] = off + v0;
        if (idx + 2 < N_ATOMS) g_row[idx + 2] = off + v0 + v1;
        if (idx + 3 < N_ATOMS) g_row[idx + 3] = off + v0 + v1 + v2;
        if (tid == 0) g_part[bid] = wsum[7];

        __threadfence();
        if (tid == 0) s_last = (atomicAdd(&g_done, 1) == SCAN_BLK - 1);
        __syncthreads();
        if (s_last) {
            __threadfence();
            if (tid < 32) {
                int lane2 = tid;
                int i = lane2 * 4;
                int u0 = (i + 0 < SCAN_BLK) ? g_part[i + 0] : 0;
                int u1 = (i + 1 < SCAN_BLK) ? g_part[i + 1] : 0;
                int u2 = (i + 2 < SCAN_BLK) ? g_part[i + 2] : 0;
                int u3 = (i + 3 < SCAN_BLK) ? g_part[i + 3] : 0;
                int ss = u0 + u1 + u2 + u3;
                int ssi = ss;
#pragma unroll
                for (int o = 1; o < 32; o <<= 1) {
                    int u = __shfl_up_sync(0xffffffffu, ssi, o);
                    if (lane2 >= o) ssi += u;
                }
                int excl = ssi - ss;
                if (i + 0 < SCAN_BLK) g_part[i + 0] = excl;
                if (i + 1 < SCAN_BLK) g_part[i + 1] = excl + u0;
                if (i + 2 < SCAN_BLK) g_part[i + 2] = excl + u0 + u1;
                if (i + 3 < SCAN_BLK) g_part[i + 3] = excl + u0 + u1 + u2;
                if (lane2 == 31) g_row[N_ATOMS] = ssi;
                __syncwarp();
                if (lane2 == 0) {
                    g_done = 0;
                    __threadfence();
                    g_flag = 1;
                }
            }
        }
        return;
    }
    if (bid < SCAN_BLK + PACK_BLK) {
        /* pack raw -> interleaved (a, delta/64) 256B rows */
        int i = (bid - SCAN_BLK) * 256 + tid;
        if (i >= NLAYERS * TBL_T * 32) return;
        int c2 = i & 31;
        int t  = (i >> 5) & (TBL_T - 1);
        int l  = i / (TBL_T * 32);
        const __half2* raw = (const __half2*)g_traw;
        __half2 a = raw[((size_t)l * TBL_T + t) * 32 + c2];
        int tn = (t + 1 < TBL_T) ? t + 1 : t;
        __half2 b = raw[((size_t)l * TBL_T + tn) * 32 + c2];
        __half2 d = __hmul2(__hsub2(b, a), __float2half2_rn(1.0f / 64.0f));
        __half2* dst = (__half2*)g_tbl2;
        dst[(((size_t)l * TBL_T + t) * 32 + c2) * 2 + 0] = a;
        dst[(((size_t)l * TBL_T + t) * 32 + c2) * 2 + 1] = d;
        return;
    }
    if (bid < SCAN_BLK + PACK_BLK + DX_BLK) {
        extern __shared__ char sm[];
        __half* sA = (__half*)(sm + SM_A_OFF);
        __half* sB = (__half*)(sm + SM_B_OFF);
        float*  sC = (float*)(sm + SM_C_OFF);
        size_t r0 = (size_t)(bid - SCAN_BLK - PACK_BLK) * 128;

        for (int i = tid; i < 128 * 64; i += 256) {
            int row = i >> 6, col = i & 63;
            size_t gr = r0 + row;
            float v = 0.0f;
            if (gr < N_ATOMS) {
                v = emb[(size_t)z[gr] * HID + col];
                g_h[gr * HID + col] = v;
            }
            sA[row * LDA + col] = __float2half_rn(v);
        }
        load_B(sB, g_cf1h, tid);
        __syncthreads();
        wmma_gemm(sA, sB, sC);
        __syncthreads();
        for (int i = tid; i < 128 * 32; i += 256) {
            int row = i >> 5, c2 = i & 31;
            size_t gr = r0 + row;
            if (gr < N_ATOMS) {
                __half2 hv = __floats2half2_rn(sC[row * LDC + c2 * 2], sC[row * LDC + c2 * 2 + 1]);
                *(__half2*)(g_x + gr * HID + c2 * 2) = hv;
            }
        }
        return;
    }
    if (tid == 0) {
        while (!*((volatile int*)&g_flag)) __nanosleep(64);
    }
    __syncthreads();
    __threadfence();
    int i = (bid - SCAN_BLK - PACK_BLK - DX_BLK) * 256 + tid;
    if (i >= N_ATOMS) return;
    int v = g_row[i] + g_part[i >> 10];
    g_row[i] = v;
    g_cur[i] = v;
}

/* =================== K3: scatter (32-bit records, 6-bit f) =============== */
__global__ void scatter_kernel(const int* __restrict__ ei) {
    int e = blockIdx.x * blockDim.x + threadIdx.x;
    if (e == 0) g_flag = 0;
    if (e >= N_EDGES) return;
    int s = ei[e];
    int t = ei[N_EDGES + e];
    float4 ps = g_pos4[s];
    float4 pt = g_pos4[t];
    float dx = ps.x - pt.x, dy = ps.y - pt.y, dz = ps.z - pt.z;
    float d = sqrtf(dx * dx + dy * dy + dz * dz);
    unsigned ti6 = min((unsigned)(d * TBL_SCALE64), (unsigned)TI6_MAX);
    int p = atomicAdd(&g_cur[t], 1);
    g_edata[p] = ((unsigned)s << 15) | ti6;
}

/* ====== K4: aggregate — half-warp/node + edata prefetch (PROFILED) ======= */
__global__ void __launch_bounds__(1024, 1) aggregate_kernel(int layer) {
    extern __shared__ __align__(16) char s_raw[];
    {
        const uint4* src = (const uint4*)(g_tbl2 + (size_t)layer * TBL_T * HID * 2);
        uint4* dst = (uint4*)s_raw;
        for (int i = threadIdx.x; i < TBL2_BYTES / 16; i += 1024) dst[i] = src[i];
    }
    __syncthreads();

    int lane = threadIdx.x & 31;
    int wib  = threadIdx.x >> 5;
    int half = lane >> 4;              /* which node of the pair          */
    int l16  = lane & 15;              /* lane within half: ch 4l..4l+3   */
    unsigned lds_off = (unsigned)l16 << 4;           /* 16B chunk in row  */
    const char* xbase = (const char*)g_x + (l16 << 3);

    for (int nodeb = blockIdx.x * 64 + wib * 2; nodeb < N_ATOMS; nodeb += gridDim.x * 64) {
        int node = nodeb + half;
        int beg = 0, end = 0;
        if (node < N_ATOMS) { beg = g_row[node]; end = g_row[node + 1]; }

        int nb = (end - beg + 15) >> 4;
        int nbmax = max(nb, __shfl_xor_sync(0xffffffffu, nb, 16));

        float accf0 = 0.0f, accf1 = 0.0f, accf2 = 0.0f, accf3 = 0.0f;

        /* prefetch batch 0 */
        int cnt = min(16, end - beg);
        unsigned pk = (nbmax > 0 && l16 < cnt) ? __ldcs(&g_edata[beg + l16]) : 0u;

        for (int b = 0; b < nbmax; b++) {
            /* prefetch batch b+1 while processing batch b */
            int basen = beg + ((b + 1) << 4);
            int cntn = min(16, end - basen);
            unsigned pknext = (b + 1 < nbmax && l16 < cntn)
                              ? __ldcs(&g_edata[basen + l16]) : 0u;

            int cmax = max(cnt, __shfl_xor_sync(0xffffffffu, cnt, 16));

            __half2 a0 = __half2half2(__ushort_as_half(0));
            __half2 a1 = a0;

#define EDGE(J) do {                                                          \
            unsigned p = __shfl_sync(0xffffffffu, pk, (J), 16);               \
            uint2 xv = make_uint2(0u, 0u);                                    \
            if ((J) < cnt)                                                    \
                xv = *(const uint2*)(xbase + ((size_t)(p >> 15) << 7));       \
            uint4 ad = *(const uint4*)(s_raw + ((p & 0x7FC0u) << 2) + lds_off); \
            __half2 f2 = __half2half2(__ushort2half_rn((unsigned short)(p & 63u))); \
            a0 = __hadd2(a0, __hmul2(__hfma2(f2, *(__half2*)&ad.y, *(__half2*)&ad.x), *(__half2*)&xv.x)); \
            a1 = __hadd2(a1, __hmul2(__hfma2(f2, *(__half2*)&ad.w, *(__half2*)&ad.z), *(__half2*)&xv.y)); \
        } while (0)

            int j = 0;
            for (; j + 4 <= cmax; j += 4) {
                EDGE(j + 0); EDGE(j + 1); EDGE(j + 2); EDGE(j + 3);
                float2 v0 = __half22float2(a0);
                float2 v1 = __half22float2(a1);
                accf0 += v0.x; accf1 += v0.y;
                accf2 += v1.x; accf3 += v1.y;
                a0 = __half2half2(__ushort_as_half(0));
                a1 = a0;
            }
            for (; j < cmax; j++) EDGE(j);
#undef EDGE
            float2 v0 = __half22float2(a0);
            float2 v1 = __half22float2(a1);
            accf0 += v0.x; accf1 += v0.y;
            accf2 += v1.x; accf3 += v1.y;

            pk = pknext;
            cnt = cntn;
        }

        if (node < N_ATOMS) {
            __half2 h0 = __floats2half2_rn(accf0, accf1);
            __half2 h1 = __floats2half2_rn(accf2, accf3);
            uint2 st;
            st.x = *(unsigned*)&h0;
            st.y = *(unsigned*)&h1;
            *(uint2*)((char*)g_aggh + (size_t)node * 128 + (l16 << 3)) = st;
        }
    }
}

/* --- h += ssp(agg@W1+b1)@W2+b2 ; x = h_new@W3 (all tensor-core) ---------- */
__global__ void __launch_bounds__(256) dense_post_w(int l, int fuse_next,
                                                    const float* __restrict__ b1,
                                                    const float* __restrict__ b2) {
    extern __shared__ char sm[];
    __half* sA = (__half*)(sm + SM_A_OFF);
    __half* sB = (__half*)(sm + SM_B_OFF);
    float*  sC = (float*)(sm + SM_C_OFF);
    int tid = threadIdx.x;
    size_t r0 = (size_t)blockIdx.x * 128;

    const __half* W1 = g_cf2h + (size_t)l * HID * HID;
    const __half* W2 = g_inth + (size_t)l * HID * HID;
    const __half* W3 = g_cf1h + (size_t)(l + 1 < NLAYERS ? l + 1 : 0) * HID * HID;

    for (int i = tid; i < 128 * 32; i += 256) {
        int row = i >> 5, c2 = i & 31;
        unsigned int v = 0;
        if (r0 + row < N_ATOMS)
            v = ((const unsigned int*)g_aggh)[(r0 + row) * 32 + c2];
        *(unsigned int*)&sA[row * LDA + c2 * 2] = v;
    }
    load_B(sB, W1, tid);
    __syncthreads();
    wmma_gemm(sA, sB, sC);
    __syncthreads();

    for (int i = tid; i < 128 * 64; i += 256) {
        int row = i >> 6, col = i & 63;
        float v = ssp(sC[row * LDC + col] + __ldg(&b1[col]));
        sA[row * LDA + col] = __float2half_rn(v);
    }
    load_B(sB, W2, tid);
    __syncthreads();
    wmma_gemm(sA, sB, sC);
    __syncthreads();

    for (int i = tid; i < 128 * 64; i += 256) {
        int row = i >> 6, col = i & 63;
        size_t gr = r0 + row;
        float v = 0.0f;
        if (gr < N_ATOMS) {
            v = g_h[gr * HID + col] + sC[row * LDC + col] + __ldg(&b2[col]);
            g_h[gr * HID + col] = v;
        }
        sA[row * LDA + col] = __float2half_rn(v);
    }
    if (!fuse_next) return;

    load_B(sB, W3, tid);
    __syncthreads();
    wmma_gemm(sA, sB, sC);
    __syncthreads();
    for (int i = tid; i < 128 * 32; i += 256) {
        int row = i >> 5, c2 = i & 31;
        size_t gr = r0 + row;
        if (gr < N_ATOMS) {
            __half2 hv = __floats2half2_rn(sC[row * LDC + c2 * 2], sC[row * LDC + c2 * 2 + 1]);
            *(__half2*)(g_x + gr * HID + c2 * 2) = hv;
        }
    }
}

/* --------------- readout: per-atom MLP (64->32->1) + molecule sum -------- */
__global__ void readout_kernel(const int* __restrict__ batch,
                               const float* __restrict__ w1, const float* __restrict__ b1,
                               const float* __restrict__ w2, const float* __restrict__ b2) {
    int warp = (blockIdx.x * blockDim.x + threadIdx.x) >> 5;
    int lane = threadIdx.x & 31;
    if (warp >= N_ATOMS) return;

    float h0 = g_h[(size_t)warp * HID + lane];
    float h1 = g_h[(size_t)warp * HID + 32 + lane];

    float acc = b1[lane];
#pragma unroll
    for (int k = 0; k < 32; k++) {
        float hk = __shfl_sync(0xffffffffu, h0, k);
        acc = fmaf(hk, w1[k * 32 + lane], acc);
    }
#pragma unroll
    for (int k = 0; k < 32; k++) {
        float hk = __shfl_sync(0xffffffffu, h1, k);
        acc = fmaf(hk, w1[(32 + k) * 32 + lane], acc);
    }
    float t = ssp(acc) * w2[lane];
#pragma unroll
    for (int o = 16; o > 0; o >>= 1) t += __shfl_xor_sync(0xffffffffu, t, o);
    if (lane == 0) atomicAdd(&g_molsum[batch[warp]], t + b2[0]);
}

/* ------- out[g] = molsum[g]*fin_w + fin_b ; self-restore molsum ---------- */
__global__ void final_kernel(const float* __restrict__ fw, const float* __restrict__ fb,
                             float* __restrict__ out) {
    int g = blockIdx.x * blockDim.x + threadIdx.x;
    if (g < N_MOL) {
        float v = g_molsum[g];
        out[g] = v * fw[0] + fb[0];
        g_molsum[g] = 0.0f;
    }
}

/* ========================================================================= */
extern "C" void kernel_launch(void* const* d_in, const int* in_sizes, int n_in,
                              void* d_out, int out_size) {
    const int*   z      = (const int*)d_in[0];
    const float* pos    = (const float*)d_in[1];
    const int*   batch  = (const int*)d_in[2];
    const int*   ei     = (const int*)d_in[3];
    const float* emb    = (const float*)d_in[4];
    const float* out_w1 = (const float*)d_in[5];
    const float* out_b1 = (const float*)d_in[6];
    const float* out_w2 = (const float*)d_in[7];
    const float* out_b2 = (const float*)d_in[8];
    const float* fin_w  = (const float*)d_in[9];
    const float* fin_b  = (const float*)d_in[10];
    const float* mlp_w1 = (const float*)d_in[11];
    const float* mlp_b1 = (const float*)d_in[12];
    const float* mlp_w2 = (const float*)d_in[13];
    const float* mlp_b2 = (const float*)d_in[14];
    const float* cf1    = (const float*)d_in[15];
    const float* cf2    = (const float*)d_in[16];
    const float* cf2b   = (const float*)d_in[17];
    const float* intw   = (const float*)d_in[18];
    const float* intb   = (const float*)d_in[19];

    (void)in_sizes; (void)n_in; (void)out_size;

    cudaFuncSetAttribute(aggregate_kernel,
                         cudaFuncAttributeMaxDynamicSharedMemorySize, TBL2_BYTES);
    cudaFuncSetAttribute(k2_scan_pack_densex,
                         cudaFuncAttributeMaxDynamicSharedMemorySize, SM_TOTAL);
    cudaFuncSetAttribute(dense_post_w,
                         cudaFuncAttributeMaxDynamicSharedMemorySize, SM_TOTAL);

    k1_prep_table_hist<<<WPREP_BLK + POS_BLK + TBL_BLK + HIST_BLK, 256>>>(
        cf1, cf2, intw, mlp_w1, mlp_b1, mlp_w2, mlp_b2, ei, pos);
    k2_scan_pack_densex<<<SCAN_BLK + PACK_BLK + DX_BLK + SCANC_BLK, 256, SM_TOTAL>>>(z, emb);
    scatter_kernel<<<(N_EDGES + 255) / 256, 256>>>(ei);

    for (int l = 0; l < NLAYERS; l++) {
        aggregate_kernel<<<AGG_BLOCKS, 1024, TBL2_BYTES>>>(l);
        dense_post_w<<<DX_BLK, 256, SM_TOTAL>>>(l, (l + 1 < NLAYERS),
                                                cf2b + (size_t)l * HID,
                                                intb + (size_t)l * HID);
    }

    int warp_blocks = (N_ATOMS * 32 + 255) / 256;
    readout_kernel<<<warp_blocks, 256>>>(batch, out_w1, out_b1, out_w2, out_b2);
    final_kernel<<<(N_MOL + 255) / 256, 256>>>(fin_w, fin_b, (float*)d_out);
}

// round 14
// speedup vs baseline: 1.0695x; 1.0037x over previous
#include <cuda_runtime.h>
#include <cuda_fp16.h>
#include <mma.h>
#include <math.h>

using namespace nvcuda;

#define N_ATOMS 100000
#define N_EDGES 3200000
#define N_MOL   2000
#define HID     64
#define NGAUSS  50
#define NLAYERS 3
#define TBL_T   512
#define TBL2_BYTES (TBL_T * HID * 4)       /* 128 KB: (a, delta/64) interleaved */
#define DMAX    8.6603f                    /* >= 5*sqrt(3) */
#define TBL_SCALE ((float)(TBL_T-1) / DMAX)
#define TBL_SCALE64 (TBL_SCALE * 64.0f)
#define TI6_MAX ((TBL_T - 2) * 64 + 63)    /* 32703 */
#define LOG2F_  0.69314718055994530942f
#define PI_OVER_CUTOFF 0.31415926535897932385f
#define SCAN_BLK 98
#define AGG_BLOCKS 148
#define TB_TPB  16
#define SENT_PK ((unsigned)N_ATOMS << 15)  /* sentinel: zero x row, ti=0, f=0 */

#define WPREP_BLK 48
#define POS_BLK   ((N_ATOMS + 255) / 256)
#define TBL_BLK   (NLAYERS * (TBL_T / TB_TPB))
#define HIST_BLK  ((N_EDGES + 255) / 256)

#define PACK_BLK  ((NLAYERS * TBL_T * 32 + 255) / 256)
#define DX_BLK    ((N_ATOMS + 127) / 128)
#define SCANC_BLK ((N_ATOMS + 255) / 256)

#define LDA 72
#define LDC 68
#define SM_A_OFF  0
#define SM_B_OFF  (128 * LDA * 2)
#define SM_C_OFF  (SM_B_OFF + 64 * LDA * 2)
#define SM_TOTAL  (SM_C_OFF + 128 * LDC * 4)

/* ------------------------- scratch (no allocs allowed) ------------------ */
__device__ int                g_hist[N_ATOMS];
__device__ int                g_row[N_ATOMS + 1];
__device__ int                g_cur[N_ATOMS];
__device__ int                g_part[128];
__device__ int                g_done;
__device__ int                g_flag;
__device__ unsigned int       g_edata[N_EDGES];      /* s:17 | ti:9 | f6:6 */
__device__ float4             g_pos4[N_ATOMS];
__device__ __align__(16)  __half g_traw[NLAYERS * TBL_T * HID];
__device__ __align__(16)  __half g_tbl2[NLAYERS * TBL_T * HID * 2];
__device__ float              g_h[(size_t)N_ATOMS * HID];
__device__ __align__(128) __half g_x[((size_t)N_ATOMS + 1) * HID]; /* +1 sentinel row */
__device__ __align__(128) __half g_aggh[(size_t)N_ATOMS * HID];
__device__ float              g_molsum[N_MOL];
__device__ __align__(16) __half g_cf1h[NLAYERS * HID * HID];
__device__ __align__(16) __half g_cf2h[NLAYERS * HID * HID];
__device__ __align__(16) __half g_inth[NLAYERS * HID * HID];

__device__ __forceinline__ float ssp(float v) {
    return fmaxf(v, 0.0f) + log1pf(expf(-fabsf(v))) - LOG2F_;
}

/* --------------- wmma 128x64x64 tile helpers ----------------------------- */
__device__ __forceinline__ void wmma_gemm(const __half* sA, const __half* sB, float* sC) {
    int w = threadIdx.x >> 5;
    wmma::fragment<wmma::accumulator, 16, 16, 16, float> c[4];
#pragma unroll
    for (int n = 0; n < 4; n++) wmma::fill_fragment(c[n], 0.0f);
#pragma unroll
    for (int k = 0; k < 4; k++) {
        wmma::fragment<wmma::matrix_a, 16, 16, 16, __half, wmma::row_major> a;
        wmma::load_matrix_sync(a, sA + (w * 16) * LDA + k * 16, LDA);
#pragma unroll
        for (int n = 0; n < 4; n++) {
            wmma::fragment<wmma::matrix_b, 16, 16, 16, __half, wmma::row_major> b;
            wmma::load_matrix_sync(b, sB + (k * 16) * LDA + n * 16, LDA);
            wmma::mma_sync(c[n], a, b, c[n]);
        }
    }
#pragma unroll
    for (int n = 0; n < 4; n++)
        wmma::store_matrix_sync(sC + (w * 16) * LDC + n * 16, c[n], LDC, wmma::mem_row_major);
}

__device__ __forceinline__ void load_B(__half* sB, const __half* W, int tid) {
    for (int i = tid; i < 64 * 32; i += 256) {
        int row = i >> 5, c2 = i & 31;
        *(unsigned int*)&sB[row * LDA + c2 * 2] = ((const unsigned int*)W)[row * 32 + c2];
    }
}

/* =========== K1: wprep + pos4 repack + table + hist (fused) ============== */
__global__ void __launch_bounds__(256) k1_prep_table_hist(
        const float* __restrict__ cf1, const float* __restrict__ cf2,
        const float* __restrict__ intw,
        const float* __restrict__ w1, const float* __restrict__ b1,
        const float* __restrict__ w2, const float* __restrict__ b2,
        const int* __restrict__ ei, const float* __restrict__ pos) {
    int bid = blockIdx.x;
    int tid = threadIdx.x;

    if (bid < WPREP_BLK) {
        /* zero the sentinel x row (128 bytes) once per launch */
        if (bid == 0 && tid < 16)
            ((uint2*)((char*)g_x + (size_t)N_ATOMS * 128))[tid] = make_uint2(0u, 0u);
        int i = bid * 256 + tid;
        if (i < NLAYERS * HID * HID) {
            g_cf1h[i] = __float2half_rn(cf1[i]);
            g_cf2h[i] = __float2half_rn(cf2[i]);
            g_inth[i] = __float2half_rn(intw[i]);
        }
        return;
    }
    if (bid < WPREP_BLK + POS_BLK) {
        int i = (bid - WPREP_BLK) * 256 + tid;
        if (i < N_ATOMS)
            g_pos4[i] = make_float4(pos[3 * i], pos[3 * i + 1], pos[3 * i + 2], 0.0f);
        return;
    }
    if (bid < WPREP_BLK + POS_BLK + TBL_BLK) {
        __shared__ float W1s[NGAUSS][HID];
        __shared__ float W2s[HID][HID];
        __shared__ float rbfs[TB_TPB][NGAUSS];
        __shared__ float tmps[TB_TPB][HID];
        int tb = bid - WPREP_BLK - POS_BLK;
        int l = tb / (TBL_T / TB_TPB);
        int tbase = (tb % (TBL_T / TB_TPB)) * TB_TPB;

        for (int i = tid; i < NGAUSS * HID; i += 256)
            W1s[i / HID][i % HID] = w1[(size_t)l * NGAUSS * HID + i];
        for (int i = tid; i < HID * HID; i += 256)
            W2s[i >> 6][i & 63] = w2[(size_t)l * HID * HID + i];
        for (int i = tid; i < TB_TPB * NGAUSS; i += 256) {
            int tt = i / NGAUSS, k = i % NGAUSS;
            float d = (float)(tbase + tt) * (DMAX / (float)(TBL_T - 1));
            float off = (float)k * (10.0f / 49.0f);
            float u = d - off;
            const float coeff = -0.5f * (49.0f / 10.0f) * (49.0f / 10.0f);
            rbfs[tt][k] = expf(coeff * u * u);
        }
        __syncthreads();

        for (int i = tid; i < TB_TPB * HID; i += 256) {
            int tt = i >> 6, j = i & 63;
            float acc = b1[l * HID + j];
#pragma unroll
            for (int k = 0; k < NGAUSS; k++) acc = fmaf(rbfs[tt][k], W1s[k][j], acc);
            tmps[tt][j] = ssp(acc);
        }
        __syncthreads();

        for (int i = tid; i < TB_TPB * HID; i += 256) {
            int tt = i >> 6, j = i & 63;
            float acc = b2[l * HID + j];
#pragma unroll
            for (int k = 0; k < HID; k++) acc = fmaf(tmps[tt][k], W2s[k][j], acc);
            float d = (float)(tbase + tt) * (DMAX / (float)(TBL_T - 1));
            float C = 0.5f * (cosf(d * PI_OVER_CUTOFF) + 1.0f);
            g_traw[((size_t)l * TBL_T + tbase + tt) * HID + j] = __float2half_rn(acc * C);
        }
        return;
    }
    int e = (bid - WPREP_BLK - POS_BLK - TBL_BLK) * 256 + tid;
    if (e < N_EDGES) atomicAdd(&g_hist[ei[N_EDGES + e]], 1);
}

/* ====== K2: scanA(+B last block) + pack + dense_x + scanC(spin) ========== */
__global__ void __launch_bounds__(256) k2_scan_pack_densex(const int* __restrict__ z,
                                                           const float* __restrict__ emb) {
    int bid = blockIdx.x;
    int tid = threadIdx.x;

    if (bid < SCAN_BLK) {
        __shared__ int wsum[8];
        __shared__ int s_last;
        int lane = tid & 31, wid = tid >> 5;
        int idx = bid * 1024 + tid * 4;

        int v0 = (idx + 0 < N_ATOMS) ? g_hist[idx + 0] : 0;
        int v1 = (idx + 1 < N_ATOMS) ? g_hist[idx + 1] : 0;
        int v2 = (idx + 2 < N_ATOMS) ? g_hist[idx + 2] : 0;
        int v3 = (idx + 3 < N_ATOMS) ? g_hist[idx + 3] : 0;
        if (idx + 0 < N_ATOMS) g_hist[idx + 0] = 0;
        if (idx + 1 < N_ATOMS) g_hist[idx + 1] = 0;
        if (idx + 2 < N_ATOMS) g_hist[idx + 2] = 0;
        if (idx + 3 < N_ATOMS) g_hist[idx + 3] = 0;

        int s = v0 + v1 + v2 + v3;
        int si = s;
#pragma unroll
        for (int o = 1; o < 32; o <<= 1) {
            int u = __shfl_up_sync(0xffffffffu, si, o);
            if (lane >= o) si += u;
        }
        if (lane == 31) wsum[wid] = si;
        __syncthreads();
        if (wid == 0 && lane < 8) {
            int w = wsum[lane];
#pragma unroll
            for (int o = 1; o < 8; o <<= 1) {
                int u = __shfl_up_sync(0x000000ffu, w, o);
                if (lane >= o) w += u;
            }
            wsum[lane] = w;
        }
        __syncthreads();
        int off = ((wid > 0) ? wsum[wid - 1] : 0) + (si - s);
        if (idx + 0 < N_ATOMS) g_row[idx + 0] = off;
        if (idx + 1 < N_ATOMS) g_row[idx + 1] = off + v0;
        if (idx + 2 < N_ATOMS) g_row[idx + 2] = off + v0 + v1;
        if (idx + 3 < N_ATOMS) g_row[idx + 3] = off + v0 + v1 + v2;
        if (tid == 0) g_part[bid] = wsum[7];

        __threadfence();
        if (tid == 0) s_last = (atomicAdd(&g_done, 1) == SCAN_BLK - 1);
        __syncthreads();
        if (s_last) {
            __threadfence();
            if (tid < 32) {
                int lane2 = tid;
                int i = lane2 * 4;
                int u0 = (i + 0 < SCAN_BLK) ? g_part[i + 0] : 0;
                int u1 = (i + 1 < SCAN_BLK) ? g_part[i + 1] : 0;
                int u2 = (i + 2 < SCAN_BLK) ? g_part[i + 2] : 0;
                int u3 = (i + 3 < SCAN_BLK) ? g_part[i + 3] : 0;
                int ss = u0 + u1 + u2 + u3;
                int ssi = ss;
#pragma unroll
                for (int o = 1; o < 32; o <<= 1) {
                    int u = __shfl_up_sync(0xffffffffu, ssi, o);
                    if (lane2 >= o) ssi += u;
                }
                int excl = ssi - ss;
                if (i + 0 < SCAN_BLK) g_part[i + 0] = excl;
                if (i + 1 < SCAN_BLK) g_part[i + 1] = excl + u0;
                if (i + 2 < SCAN_BLK) g_part[i + 2] = excl + u0 + u1;
                if (i + 3 < SCAN_BLK) g_part[i + 3] = excl + u0 + u1 + u2;
                if (lane2 == 31) g_row[N_ATOMS] = ssi;
                __syncwarp();
                if (lane2 == 0) {
                    g_done = 0;
                    __threadfence();
                    g_flag = 1;
                }
            }
        }
        return;
    }
    if (bid < SCAN_BLK + PACK_BLK) {
        /* pack raw -> interleaved (a, delta/64) 256B rows */
        int i = (bid - SCAN_BLK) * 256 + tid;
        if (i >= NLAYERS * TBL_T * 32) return;
        int c2 = i & 31;
        int t  = (i >> 5) & (TBL_T - 1);
        int l  = i / (TBL_T * 32);
        const __half2* raw = (const __half2*)g_traw;
        __half2 a = raw[((size_t)l * TBL_T + t) * 32 + c2];
        int tn = (t + 1 < TBL_T) ? t + 1 : t;
        __half2 b = raw[((size_t)l * TBL_T + tn) * 32 + c2];
        __half2 d = __hmul2(__hsub2(b, a), __float2half2_rn(1.0f / 64.0f));
        __half2* dst = (__half2*)g_tbl2;
        dst[(((size_t)l * TBL_T + t) * 32 + c2) * 2 + 0] = a;
        dst[(((size_t)l * TBL_T + t) * 32 + c2) * 2 + 1] = d;
        return;
    }
    if (bid < SCAN_BLK + PACK_BLK + DX_BLK) {
        extern __shared__ char sm[];
        __half* sA = (__half*)(sm + SM_A_OFF);
        __half* sB = (__half*)(sm + SM_B_OFF);
        float*  sC = (float*)(sm + SM_C_OFF);
        size_t r0 = (size_t)(bid - SCAN_BLK - PACK_BLK) * 128;

        for (int i = tid; i < 128 * 64; i += 256) {
            int row = i >> 6, col = i & 63;
            size_t gr = r0 + row;
            float v = 0.0f;
            if (gr < N_ATOMS) {
                v = emb[(size_t)z[gr] * HID + col];
                g_h[gr * HID + col] = v;
            }
            sA[row * LDA + col] = __float2half_rn(v);
        }
        load_B(sB, g_cf1h, tid);
        __syncthreads();
        wmma_gemm(sA, sB, sC);
        __syncthreads();
        for (int i = tid; i < 128 * 32; i += 256) {
            int row = i >> 5, c2 = i & 31;
            size_t gr = r0 + row;
            if (gr < N_ATOMS) {
                __half2 hv = __floats2half2_rn(sC[row * LDC + c2 * 2], sC[row * LDC + c2 * 2 + 1]);
                *(__half2*)(g_x + gr * HID + c2 * 2) = hv;
            }
        }
        return;
    }
    if (tid == 0) {
        while (!*((volatile int*)&g_flag)) __nanosleep(64);
    }
    __syncthreads();
    __threadfence();
    int i = (bid - SCAN_BLK - PACK_BLK - DX_BLK) * 256 + tid;
    if (i >= N_ATOMS) return;
    int v = g_row[i] + g_part[i >> 10];
    g_row[i] = v;
    g_cur[i] = v;
}

/* =================== K3: scatter (32-bit records, 6-bit f) =============== */
__global__ void scatter_kernel(const int* __restrict__ ei) {
    int e = blockIdx.x * blockDim.x + threadIdx.x;
    if (e == 0) g_flag = 0;
    if (e >= N_EDGES) return;
    int s = ei[e];
    int t = ei[N_EDGES + e];
    float4 ps = g_pos4[s];
    float4 pt = g_pos4[t];
    float dx = ps.x - pt.x, dy = ps.y - pt.y, dz = ps.z - pt.z;
    float d = sqrtf(dx * dx + dy * dy + dz * dz);
    unsigned ti6 = min((unsigned)(d * TBL_SCALE64), (unsigned)TI6_MAX);
    int p = atomicAdd(&g_cur[t], 1);
    g_edata[p] = ((unsigned)s << 15) | ti6;
}

/* ====== K4: aggregate — half-warp/node, sentinel edges (PROFILED) ======== */
__global__ void __launch_bounds__(1024, 1) aggregate_kernel(int layer) {
    extern __shared__ __align__(16) char s_raw[];
    {
        const uint4* src = (const uint4*)(g_tbl2 + (size_t)layer * TBL_T * HID * 2);
        uint4* dst = (uint4*)s_raw;
        for (int i = threadIdx.x; i < TBL2_BYTES / 16; i += 1024) dst[i] = src[i];
    }
    __syncthreads();

    int lane = threadIdx.x & 31;
    int wib  = threadIdx.x >> 5;
    int half = lane >> 4;              /* which node of the pair          */
    int l16  = lane & 15;              /* lane within half: ch 4l..4l+3   */
    unsigned lds_off = (unsigned)l16 << 4;           /* 16B chunk in row  */
    const char* xbase = (const char*)g_x + (l16 << 3);

    for (int nodeb = blockIdx.x * 64 + wib * 2; nodeb < N_ATOMS; nodeb += gridDim.x * 64) {
        int node = nodeb + half;
        int beg = 0, end = 0;
        if (node < N_ATOMS) { beg = g_row[node]; end = g_row[node + 1]; }

        int nb = (end - beg + 15) >> 4;
        int nbmax = max(nb, __shfl_xor_sync(0xffffffffu, nb, 16));

        float accf0 = 0.0f, accf1 = 0.0f, accf2 = 0.0f, accf3 = 0.0f;

        for (int b = 0; b < nbmax; b++) {
            int idx = beg + (b << 4) + l16;
            unsigned pk = (idx < end) ? __ldcs(&g_edata[idx]) : SENT_PK;

#define EDGE(J, A0, A1) do {                                                  \
            unsigned p = __shfl_sync(0xffffffffu, pk, (J), 16);               \
            uint2 xv = *(const uint2*)(xbase + ((size_t)(p >> 15) << 7));     \
            uint4 ad = *(const uint4*)(s_raw + ((p & 0x7FC0u) << 2) + lds_off); \
            __half2 f2 = __half2half2(__ushort2half_rn((unsigned short)(p & 63u))); \
            A0 = __hadd2(A0, __hmul2(__hfma2(f2, *(__half2*)&ad.y, *(__half2*)&ad.x), *(__half2*)&xv.x)); \
            A1 = __hadd2(A1, __hmul2(__hfma2(f2, *(__half2*)&ad.w, *(__half2*)&ad.z), *(__half2*)&xv.y)); \
        } while (0)

#pragma unroll
            for (int g = 0; g < 4; g++) {
                __half2 a0 = __half2half2(__ushort_as_half(0));
                __half2 a1 = a0;
                EDGE(4 * g + 0, a0, a1);
                EDGE(4 * g + 1, a0, a1);
                EDGE(4 * g + 2, a0, a1);
                EDGE(4 * g + 3, a0, a1);
                float2 v0 = __half22float2(a0);
                float2 v1 = __half22float2(a1);
                accf0 += v0.x; accf1 += v0.y;
                accf2 += v1.x; accf3 += v1.y;
            }
#undef EDGE
        }

        if (node < N_ATOMS) {
            __half2 h0 = __floats2half2_rn(accf0, accf1);
            __half2 h1 = __floats2half2_rn(accf2, accf3);
            uint2 st;
            st.x = *(unsigned*)&h0;
            st.y = *(unsigned*)&h1;
            *(uint2*)((char*)g_aggh + (size_t)node * 128 + (l16 << 3)) = st;
        }
    }
}

/* --- h += ssp(agg@W1+b1)@W2+b2 ; x = h_new@W3 (all tensor-core) ---------- */
__global__ void __launch_bounds__(256) dense_post_w(int l, int fuse_next,
                                                    const float* __restrict__ b1,
                                                    const float* __restrict__ b2) {
    extern __shared__ char sm[];
    __half* sA = (__half*)(sm + SM_A_OFF);
    __half* sB = (__half*)(sm + SM_B_OFF);
    float*  sC = (float*)(sm + SM_C_OFF);
    int tid = threadIdx.x;
    size_t r0 = (size_t)blockIdx.x * 128;

    const __half* W1 = g_cf2h + (size_t)l * HID * HID;
    const __half* W2 = g_inth + (size_t)l * HID * HID;
    const __half* W3 = g_cf1h + (size_t)(l + 1 < NLAYERS ? l + 1 : 0) * HID * HID;

    for (int i = tid; i < 128 * 32; i += 256) {
        int row = i >> 5, c2 = i & 31;
        unsigned int v = 0;
        if (r0 + row < N_ATOMS)
            v = ((const unsigned int*)g_aggh)[(r0 + row) * 32 + c2];
        *(unsigned int*)&sA[row * LDA + c2 * 2] = v;
    }
    load_B(sB, W1, tid);
    __syncthreads();
    wmma_gemm(sA, sB, sC);
    __syncthreads();

    for (int i = tid; i < 128 * 64; i += 256) {
        int row = i >> 6, col = i & 63;
        float v = ssp(sC[row * LDC + col] + __ldg(&b1[col]));
        sA[row * LDA + col] = __float2half_rn(v);
    }
    load_B(sB, W2, tid);
    __syncthreads();
    wmma_gemm(sA, sB, sC);
    __syncthreads();

    for (int i = tid; i < 128 * 64; i += 256) {
        int row = i >> 6, col = i & 63;
        size_t gr = r0 + row;
        float v = 0.0f;
        if (gr < N_ATOMS) {
            v = g_h[gr * HID + col] + sC[row * LDC + col] + __ldg(&b2[col]);
            g_h[gr * HID + col] = v;
        }
        sA[row * LDA + col] = __float2half_rn(v);
    }
    if (!fuse_next) return;

    load_B(sB, W3, tid);
    __syncthreads();
    wmma_gemm(sA, sB, sC);
    __syncthreads();
    for (int i = tid; i < 128 * 32; i += 256) {
        int row = i >> 5, c2 = i & 31;
        size_t gr = r0 + row;
        if (gr < N_ATOMS) {
            __half2 hv = __floats2half2_rn(sC[row * LDC + c2 * 2], sC[row * LDC + c2 * 2 + 1]);
            *(__half2*)(g_x + gr * HID + c2 * 2) = hv;
        }
    }
}

/* --------------- readout: per-atom MLP (64->32->1) + molecule sum -------- */
__global__ void readout_kernel(const int* __restrict__ batch,
                               const float* __restrict__ w1, const float* __restrict__ b1,
                               const float* __restrict__ w2, const float* __restrict__ b2) {
    int warp = (blockIdx.x * blockDim.x + threadIdx.x) >> 5;
    int lane = threadIdx.x & 31;
    if (warp >= N_ATOMS) return;

    float h0 = g_h[(size_t)warp * HID + lane];
    float h1 = g_h[(size_t)warp * HID + 32 + lane];

    float acc = b1[lane];
#pragma unroll
    for (int k = 0; k < 32; k++) {
        float hk = __shfl_sync(0xffffffffu, h0, k);
        acc = fmaf(hk, w1[k * 32 + lane], acc);
    }
#pragma unroll
    for (int k = 0; k < 32; k++) {
        float hk = __shfl_sync(0xffffffffu, h1, k);
        acc = fmaf(hk, w1[(32 + k) * 32 + lane], acc);
    }
    float t = ssp(acc) * w2[lane];
#pragma unroll
    for (int o = 16; o > 0; o >>= 1) t += __shfl_xor_sync(0xffffffffu, t, o);
    if (lane == 0) atomicAdd(&g_molsum[batch[warp]], t + b2[0]);
}

/* ------- out[g] = molsum[g]*fin_w + fin_b ; self-restore molsum ---------- */
__global__ void final_kernel(const float* __restrict__ fw, const float* __restrict__ fb,
                             float* __restrict__ out) {
    int g = blockIdx.x * blockDim.x + threadIdx.x;
    if (g < N_MOL) {
        float v = g_molsum[g];
        out[g] = v * fw[0] + fb[0];
        g_molsum[g] = 0.0f;
    }
}

/* ========================================================================= */
extern "C" void kernel_launch(void* const* d_in, const int* in_sizes, int n_in,
                              void* d_out, int out_size) {
    const int*   z      = (const int*)d_in[0];
    const float* pos    = (const float*)d_in[1];
    const int*   batch  = (const int*)d_in[2];
    const int*   ei     = (const int*)d_in[3];
    const float* emb    = (const float*)d_in[4];
    const float* out_w1 = (const float*)d_in[5];
    const float* out_b1 = (const float*)d_in[6];
    const float* out_w2 = (const float*)d_in[7];
    const float* out_b2 = (const float*)d_in[8];
    const float* fin_w  = (const float*)d_in[9];
    const float* fin_b  = (const float*)d_in[10];
    const float* mlp_w1 = (const float*)d_in[11];
    const float* mlp_b1 = (const float*)d_in[12];
    const float* mlp_w2 = (const float*)d_in[13];
    const float* mlp_b2 = (const float*)d_in[14];
    const float* cf1    = (const float*)d_in[15];
    const float* cf2    = (const float*)d_in[16];
    const float* cf2b   = (const float*)d_in[17];
    const float* intw   = (const float*)d_in[18];
    const float* intb   = (const float*)d_in[19];

    (void)in_sizes; (void)n_in; (void)out_size;

    cudaFuncSetAttribute(aggregate_kernel,
                         cudaFuncAttributeMaxDynamicSharedMemorySize, TBL2_BYTES);
    cudaFuncSetAttribute(k2_scan_pack_densex,
                         cudaFuncAttributeMaxDynamicSharedMemorySize, SM_TOTAL);
    cudaFuncSetAttribute(dense_post_w,
                         cudaFuncAttributeMaxDynamicSharedMemorySize, SM_TOTAL);

    k1_prep_table_hist<<<WPREP_BLK + POS_BLK + TBL_BLK + HIST_BLK, 256>>>(
        cf1, cf2, intw, mlp_w1, mlp_b1, mlp_w2, mlp_b2, ei, pos);
    k2_scan_pack_densex<<<SCAN_BLK + PACK_BLK + DX_BLK + SCANC_BLK, 256, SM_TOTAL>>>(z, emb);
    scatter_kernel<<<(N_EDGES + 255) / 256, 256>>>(ei);

    for (int l = 0; l < NLAYERS; l++) {
        aggregate_kernel<<<AGG_BLOCKS, 1024, TBL2_BYTES>>>(l);
        dense_post_w<<<DX_BLK, 256, SM_TOTAL>>>(l, (l + 1 < NLAYERS),
                                                cf2b + (size_t)l * HID,
                                                intb + (size_t)l * HID);
    }

    int warp_blocks = (N_ATOMS * 32 + 255) / 256;
    readout_kernel<<<warp_blocks, 256>>>(batch, out_w1, out_b1, out_w2, out_b2);
    final_kernel<<<(N_MOL + 255) / 256, 256>>>(fin_w, fin_b, (float*)d_out);
}

// round 15
// speedup vs baseline: 1.0903x; 1.0194x over previous
#include <cuda_runtime.h>
#include <cuda_fp16.h>
#include <mma.h>
#include <math.h>

using namespace nvcuda;

#define N_ATOMS 100000
#define N_EDGES 3200000
#define N_MOL   2000
#define HID     64
#define NGAUSS  50
#define NLAYERS 3
#define TBL_T   512
#define TBL2_BYTES (TBL_T * HID * 4)       /* 128 KB: (a, delta/64) interleaved */
#define DMAX    8.6603f                    /* >= 5*sqrt(3) */
#define TBL_SCALE ((float)(TBL_T-1) / DMAX)
#define TBL_SCALE64 (TBL_SCALE * 64.0f)
#define TI6_MAX ((TBL_T - 2) * 64 + 63)    /* 32703 */
#define LOG2F_  0.69314718055994530942f
#define PI_OVER_CUTOFF 0.31415926535897932385f
#define SCAN_BLK 98
#define AGG_BLOCKS 148
#define TB_TPB  16

#define WPREP_BLK 48
#define POS_BLK   ((N_ATOMS + 255) / 256)
#define TBL_BLK   (NLAYERS * (TBL_T / TB_TPB))
#define HIST_BLK  ((N_EDGES + 255) / 256)

#define PACK_BLK  ((NLAYERS * TBL_T * 32 + 255) / 256)
#define DX_BLK    ((N_ATOMS + 127) / 128)
#define SCANC_BLK ((N_ATOMS + 255) / 256)

#define LDA 72
#define LDC 68
#define SM_A_OFF  0
#define SM_B_OFF  (128 * LDA * 2)
#define SM_C_OFF  (SM_B_OFF + 64 * LDA * 2)
#define SM_TOTAL  (SM_C_OFF + 128 * LDC * 4)

/* ------------------------- scratch (no allocs allowed) ------------------ */
__device__ int                g_hist[N_ATOMS];
__device__ int                g_row[N_ATOMS + 1];
__device__ int                g_cur[N_ATOMS];
__device__ int                g_part[128];
__device__ int                g_done;
__device__ int                g_flag;
__device__ unsigned int       g_edata[N_EDGES];      /* s:17 | ti:9 | f6:6 */
__device__ float4             g_pos4[N_ATOMS];
__device__ __align__(16)  __half g_traw[NLAYERS * TBL_T * HID];
__device__ __align__(16)  __half g_tbl2[NLAYERS * TBL_T * HID * 2];
__device__ float              g_h[(size_t)N_ATOMS * HID];
__device__ __align__(128) __half g_x[(size_t)N_ATOMS * HID];
__device__ __align__(128) __half g_aggh[(size_t)N_ATOMS * HID];
__device__ float              g_molsum[N_MOL];
__device__ __align__(16) __half g_cf1h[NLAYERS * HID * HID];
__device__ __align__(16) __half g_cf2h[NLAYERS * HID * HID];
__device__ __align__(16) __half g_inth[NLAYERS * HID * HID];

__device__ __forceinline__ float ssp(float v) {
    return fmaxf(v, 0.0f) + log1pf(expf(-fabsf(v))) - LOG2F_;
}

/* --------------- wmma 128x64x64 tile helpers ----------------------------- */
__device__ __forceinline__ void wmma_gemm(const __half* sA, const __half* sB, float* sC) {
    int w = threadIdx.x >> 5;
    wmma::fragment<wmma::accumulator, 16, 16, 16, float> c[4];
#pragma unroll
    for (int n = 0; n < 4; n++) wmma::fill_fragment(c[n], 0.0f);
#pragma unroll
    for (int k = 0; k < 4; k++) {
        wmma::fragment<wmma::matrix_a, 16, 16, 16, __half, wmma::row_major> a;
        wmma::load_matrix_sync(a, sA + (w * 16) * LDA + k * 16, LDA);
#pragma unroll
        for (int n = 0; n < 4; n++) {
            wmma::fragment<wmma::matrix_b, 16, 16, 16, __half, wmma::row_major> b;
            wmma::load_matrix_sync(b, sB + (k * 16) * LDA + n * 16, LDA);
            wmma::mma_sync(c[n], a, b, c[n]);
        }
    }
#pragma unroll
    for (int n = 0; n < 4; n++)
        wmma::store_matrix_sync(sC + (w * 16) * LDC + n * 16, c[n], LDC, wmma::mem_row_major);
}

__device__ __forceinline__ void load_B(__half* sB, const __half* W, int tid) {
    for (int i = tid; i < 64 * 32; i += 256) {
        int row = i >> 5, c2 = i & 31;
        *(unsigned int*)&sB[row * LDA + c2 * 2] = ((const unsigned int*)W)[row * 32 + c2];
    }
}

/* =========== K1: wprep + pos4 repack + table + hist (fused) ============== */
__global__ void __launch_bounds__(256) k1_prep_table_hist(
        const float* __restrict__ cf1, const float* __restrict__ cf2,
        const float* __restrict__ intw,
        const float* __restrict__ w1, const float* __restrict__ b1,
        const float* __restrict__ w2, const float* __restrict__ b2,
        const int* __restrict__ ei, const float* __restrict__ pos) {
    int bid = blockIdx.x;
    int tid = threadIdx.x;

    if (bid < WPREP_BLK) {
        int i = bid * 256 + tid;
        if (i < NLAYERS * HID * HID) {
            g_cf1h[i] = __float2half_rn(cf1[i]);
            g_cf2h[i] = __float2half_rn(cf2[i]);
            g_inth[i] = __float2half_rn(intw[i]);
        }
        return;
    }
    if (bid < WPREP_BLK + POS_BLK) {
        int i = (bid - WPREP_BLK) * 256 + tid;
        if (i < N_ATOMS)
            g_pos4[i] = make_float4(pos[3 * i], pos[3 * i + 1], pos[3 * i + 2], 0.0f);
        return;
    }
    if (bid < WPREP_BLK + POS_BLK + TBL_BLK) {
        __shared__ float W1s[NGAUSS][HID];
        __shared__ float W2s[HID][HID];
        __shared__ float rbfs[TB_TPB][NGAUSS];
        __shared__ float tmps[TB_TPB][HID];
        int tb = bid - WPREP_BLK - POS_BLK;
        int l = tb / (TBL_T / TB_TPB);
        int tbase = (tb % (TBL_T / TB_TPB)) * TB_TPB;

        for (int i = tid; i < NGAUSS * HID; i += 256)
            W1s[i / HID][i % HID] = w1[(size_t)l * NGAUSS * HID + i];
        for (int i = tid; i < HID * HID; i += 256)
            W2s[i >> 6][i & 63] = w2[(size_t)l * HID * HID + i];
        for (int i = tid; i < TB_TPB * NGAUSS; i += 256) {
            int tt = i / NGAUSS, k = i % NGAUSS;
            float d = (float)(tbase + tt) * (DMAX / (float)(TBL_T - 1));
            float off = (float)k * (10.0f / 49.0f);
            float u = d - off;
            const float coeff = -0.5f * (49.0f / 10.0f) * (49.0f / 10.0f);
            rbfs[tt][k] = expf(coeff * u * u);
        }
        __syncthreads();

        for (int i = tid; i < TB_TPB * HID; i += 256) {
            int tt = i >> 6, j = i & 63;
            float acc = b1[l * HID + j];
#pragma unroll
            for (int k = 0; k < NGAUSS; k++) acc = fmaf(rbfs[tt][k], W1s[k][j], acc);
            tmps[tt][j] = ssp(acc);
        }
        __syncthreads();

        for (int i = tid; i < TB_TPB * HID; i += 256) {
            int tt = i >> 6, j = i & 63;
            float acc = b2[l * HID + j];
#pragma unroll
            for (int k = 0; k < HID; k++) acc = fmaf(tmps[tt][k], W2s[k][j], acc);
            float d = (float)(tbase + tt) * (DMAX / (float)(TBL_T - 1));
            float C = 0.5f * (cosf(d * PI_OVER_CUTOFF) + 1.0f);
            g_traw[((size_t)l * TBL_T + tbase + tt) * HID + j] = __float2half_rn(acc * C);
        }
        return;
    }
    int e = (bid - WPREP_BLK - POS_BLK - TBL_BLK) * 256 + tid;
    if (e < N_EDGES) atomicAdd(&g_hist[ei[N_EDGES + e]], 1);
}

/* ====== K2: scanA(+B last block) + pack + dense_x + scanC(spin) ========== */
__global__ void __launch_bounds__(256) k2_scan_pack_densex(const int* __restrict__ z,
                                                           const float* __restrict__ emb) {
    int bid = blockIdx.x;
    int tid = threadIdx.x;

    if (bid < SCAN_BLK) {
        __shared__ int wsum[8];
        __shared__ int s_last;
        int lane = tid & 31, wid = tid >> 5;
        int idx = bid * 1024 + tid * 4;

        int v0 = (idx + 0 < N_ATOMS) ? g_hist[idx + 0] : 0;
        int v1 = (idx + 1 < N_ATOMS) ? g_hist[idx + 1] : 0;
        int v2 = (idx + 2 < N_ATOMS) ? g_hist[idx + 2] : 0;
        int v3 = (idx + 3 < N_ATOMS) ? g_hist[idx + 3] : 0;
        if (idx + 0 < N_ATOMS) g_hist[idx + 0] = 0;
        if (idx + 1 < N_ATOMS) g_hist[idx + 1] = 0;
        if (idx + 2 < N_ATOMS) g_hist[idx + 2] = 0;
        if (idx + 3 < N_ATOMS) g_hist[idx + 3] = 0;

        int s = v0 + v1 + v2 + v3;
        int si = s;
#pragma unroll
        for (int o = 1; o < 32; o <<= 1) {
            int u = __shfl_up_sync(0xffffffffu, si, o);
            if (lane >= o) si += u;
        }
        if (lane == 31) wsum[wid] = si;
        __syncthreads();
        if (wid == 0 && lane < 8) {
            int w = wsum[lane];
#pragma unroll
            for (int o = 1; o < 8; o <<= 1) {
                int u = __shfl_up_sync(0x000000ffu, w, o);
                if (lane >= o) w += u;
            }
            wsum[lane] = w;
        }
        __syncthreads();
        int off = ((wid > 0) ? wsum[wid - 1] : 0) + (si - s);
        if (idx + 0 < N_ATOMS) g_row[idx + 0] = off;
        if (idx + 1 < N_ATOMS) g_row[idx + 1] = off + v0;
        if (idx + 2 < N_ATOMS) g_row[idx + 2] = off + v0 + v1;
        if (idx + 3 < N_ATOMS) g_row[idx + 3] = off + v0 + v1 + v2;
        if (tid == 0) g_part[bid] = wsum[7];

        __threadfence();
        if (tid == 0) s_last = (atomicAdd(&g_done, 1) == SCAN_BLK - 1);
        __syncthreads();
        if (s_last) {
            __threadfence();
            if (tid < 32) {
                int lane2 = tid;
                int i = lane2 * 4;
                int u0 = (i + 0 < SCAN_BLK) ? g_part[i + 0] : 0;
                int u1 = (i + 1 < SCAN_BLK) ? g_part[i + 1] : 0;
                int u2 = (i + 2 < SCAN_BLK) ? g_part[i + 2] : 0;
                int u3 = (i + 3 < SCAN_BLK) ? g_part[i + 3] : 0;
                int ss = u0 + u1 + u2 + u3;
                int ssi = ss;
#pragma unroll
                for (int o = 1; o < 32; o <<= 1) {
                    int u = __shfl_up_sync(0xffffffffu, ssi, o);
                    if (lane2 >= o) ssi += u;
                }
                int excl = ssi - ss;
                if (i + 0 < SCAN_BLK) g_part[i + 0] = excl;
                if (i + 1 < SCAN_BLK) g_part[i + 1] = excl + u0;
                if (i + 2 < SCAN_BLK) g_part[i + 2] = excl + u0 + u1;
                if (i + 3 < SCAN_BLK) g_part[i + 3] = excl + u0 + u1 + u2;
                if (lane2 == 31) g_row[N_ATOMS] = ssi;
                __syncwarp();
                if (lane2 == 0) {
                    g_done = 0;
                    __threadfence();
                    g_flag = 1;
                }
            }
        }
        return;
    }
    if (bid < SCAN_BLK + PACK_BLK) {
        /* pack raw -> interleaved (a, delta/64) 256B rows */
        int i = (bid - SCAN_BLK) * 256 + tid;
        if (i >= NLAYERS * TBL_T * 32) return;
        int c2 = i & 31;
        int t  = (i >> 5) & (TBL_T - 1);
        int l  = i / (TBL_T * 32);
        const __half2* raw = (const __half2*)g_traw;
        __half2 a = raw[((size_t)l * TBL_T + t) * 32 + c2];
        int tn = (t + 1 < TBL_T) ? t + 1 : t;
        __half2 b = raw[((size_t)l * TBL_T + tn) * 32 + c2];
        __half2 d = __hmul2(__hsub2(b, a), __float2half2_rn(1.0f / 64.0f));
        __half2* dst = (__half2*)g_tbl2;
        dst[(((size_t)l * TBL_T + t) * 32 + c2) * 2 + 0] = a;
        dst[(((size_t)l * TBL_T + t) * 32 + c2) * 2 + 1] = d;
        return;
    }
    if (bid < SCAN_BLK + PACK_BLK + DX_BLK) {
        extern __shared__ char sm[];
        __half* sA = (__half*)(sm + SM_A_OFF);
        __half* sB = (__half*)(sm + SM_B_OFF);
        float*  sC = (float*)(sm + SM_C_OFF);
        size_t r0 = (size_t)(bid - SCAN_BLK - PACK_BLK) * 128;

        for (int i = tid; i < 128 * 64; i += 256) {
            int row = i >> 6, col = i & 63;
            size_t gr = r0 + row;
            float v = 0.0f;
            if (gr < N_ATOMS) {
                v = emb[(size_t)z[gr] * HID + col];
                g_h[gr * HID + col] = v;
            }
            sA[row * LDA + col] = __float2half_rn(v);
        }
        load_B(sB, g_cf1h, tid);
        __syncthreads();
        wmma_gemm(sA, sB, sC);
        __syncthreads();
        for (int i = tid; i < 128 * 32; i += 256) {
            int row = i >> 5, c2 = i & 31;
            size_t gr = r0 + row;
            if (gr < N_ATOMS) {
                __half2 hv = __floats2half2_rn(sC[row * LDC + c2 * 2], sC[row * LDC + c2 * 2 + 1]);
                *(__half2*)(g_x + gr * HID + c2 * 2) = hv;
            }
        }
        return;
    }
    if (tid == 0) {
        while (!*((volatile int*)&g_flag)) __nanosleep(64);
    }
    __syncthreads();
    __threadfence();
    int i = (bid - SCAN_BLK - PACK_BLK - DX_BLK) * 256 + tid;
    if (i >= N_ATOMS) return;
    int v = g_row[i] + g_part[i >> 10];
    g_row[i] = v;
    g_cur[i] = v;
}

/* =================== K3: scatter (32-bit records, 6-bit f) =============== */
__global__ void scatter_kernel(const int* __restrict__ ei) {
    int e = blockIdx.x * blockDim.x + threadIdx.x;
    if (e == 0) g_flag = 0;
    if (e >= N_EDGES) return;
    int s = ei[e];
    int t = ei[N_EDGES + e];
    float4 ps = g_pos4[s];
    float4 pt = g_pos4[t];
    float dx = ps.x - pt.x, dy = ps.y - pt.y, dz = ps.z - pt.z;
    float d = sqrtf(dx * dx + dy * dy + dz * dz);
    unsigned ti6 = min((unsigned)(d * TBL_SCALE64), (unsigned)TI6_MAX);
    int p = atomicAdd(&g_cur[t], 1);
    g_edata[p] = ((unsigned)s << 15) | ti6;
}

/* ====== K4: aggregate — half-warp/node, 8-edge flush (PROFILED) ========== */
__global__ void __launch_bounds__(1024, 1) aggregate_kernel(int layer) {
    extern __shared__ __align__(16) char s_raw[];
    {
        const uint4* src = (const uint4*)(g_tbl2 + (size_t)layer * TBL_T * HID * 2);
        uint4* dst = (uint4*)s_raw;
        for (int i = threadIdx.x; i < TBL2_BYTES / 16; i += 1024) dst[i] = src[i];
    }
    __syncthreads();

    int lane = threadIdx.x & 31;
    int wib  = threadIdx.x >> 5;
    int half = lane >> 4;              /* which node of the pair          */
    int l16  = lane & 15;              /* lane within half: ch 4l..4l+3   */
    unsigned lds_off = (unsigned)l16 << 4;           /* 16B chunk in row  */
    const char* xbase = (const char*)g_x + (l16 << 3);

    for (int nodeb = blockIdx.x * 64 + wib * 2; nodeb < N_ATOMS; nodeb += gridDim.x * 64) {
        int node = nodeb + half;
        int beg = 0, end = 0;
        if (node < N_ATOMS) { beg = g_row[node]; end = g_row[node + 1]; }

        int nb = (end - beg + 15) >> 4;
        int nbmax = max(nb, __shfl_xor_sync(0xffffffffu, nb, 16));

        float accf0 = 0.0f, accf1 = 0.0f, accf2 = 0.0f, accf3 = 0.0f;

        for (int b = 0; b < nbmax; b++) {
            int base = beg + (b << 4);
            int cnt = min(16, end - base);
            unsigned pk = (lane < 16 ? (l16 < cnt) : (l16 < cnt))
                          && (l16 < cnt) ? __ldcs(&g_edata[base + l16]) : 0u;
            int cmax = max(cnt, __shfl_xor_sync(0xffffffffu, cnt, 16));

            __half2 a0 = __half2half2(__ushort_as_half(0));
            __half2 a1 = a0;

#define EDGE(J) do {                                                          \
            unsigned p = __shfl_sync(0xffffffffu, pk, (J), 16);               \
            uint2 xv = make_uint2(0u, 0u);                                    \
            if ((J) < cnt)                                                    \
                xv = *(const uint2*)(xbase + ((size_t)(p >> 15) << 7));       \
            uint4 ad = *(const uint4*)(s_raw + ((p & 0x7FC0u) << 2) + lds_off); \
            __half2 f2 = __half2half2(__ushort2half_rn((unsigned short)(p & 63u))); \
            a0 = __hadd2(a0, __hmul2(__hfma2(f2, *(__half2*)&ad.y, *(__half2*)&ad.x), *(__half2*)&xv.x)); \
            a1 = __hadd2(a1, __hmul2(__hfma2(f2, *(__half2*)&ad.w, *(__half2*)&ad.z), *(__half2*)&xv.y)); \
        } while (0)

            int j = 0;
            for (; j + 8 <= cmax; j += 8) {
                EDGE(j + 0); EDGE(j + 1); EDGE(j + 2); EDGE(j + 3);
                EDGE(j + 4); EDGE(j + 5); EDGE(j + 6); EDGE(j + 7);
                float2 v0 = __half22float2(a0);
                float2 v1 = __half22float2(a1);
                accf0 += v0.x; accf1 += v0.y;
                accf2 += v1.x; accf3 += v1.y;
                a0 = __half2half2(__ushort_as_half(0));
                a1 = a0;
            }
            for (; j < cmax; j++) EDGE(j);
#undef EDGE
            float2 v0 = __half22float2(a0);
            float2 v1 = __half22float2(a1);
            accf0 += v0.x; accf1 += v0.y;
            accf2 += v1.x; accf3 += v1.y;
        }

        if (node < N_ATOMS) {
            __half2 h0 = __floats2half2_rn(accf0, accf1);
            __half2 h1 = __floats2half2_rn(accf2, accf3);
            uint2 st;
            st.x = *(unsigned*)&h0;
            st.y = *(unsigned*)&h1;
            *(uint2*)((char*)g_aggh + (size_t)node * 128 + (l16 << 3)) = st;
        }
    }
}

/* --- h += ssp(agg@W1+b1)@W2+b2 ; x = h_new@W3 (all tensor-core) ---------- */
__global__ void __launch_bounds__(256) dense_post_w(int l, int fuse_next,
                                                    const float* __restrict__ b1,
                                                    const float* __restrict__ b2) {
    extern __shared__ char sm[];
    __half* sA = (__half*)(sm + SM_A_OFF);
    __half* sB = (__half*)(sm + SM_B_OFF);
    float*  sC = (float*)(sm + SM_C_OFF);
    int tid = threadIdx.x;
    size_t r0 = (size_t)blockIdx.x * 128;

    const __half* W1 = g_cf2h + (size_t)l * HID * HID;
    const __half* W2 = g_inth + (size_t)l * HID * HID;
    const __half* W3 = g_cf1h + (size_t)(l + 1 < NLAYERS ? l + 1 : 0) * HID * HID;

    for (int i = tid; i < 128 * 32; i += 256) {
        int row = i >> 5, c2 = i & 31;
        unsigned int v = 0;
        if (r0 + row < N_ATOMS)
            v = ((const unsigned int*)g_aggh)[(r0 + row) * 32 + c2];
        *(unsigned int*)&sA[row * LDA + c2 * 2] = v;
    }
    load_B(sB, W1, tid);
    __syncthreads();
    wmma_gemm(sA, sB, sC);
    __syncthreads();

    for (int i = tid; i < 128 * 64; i += 256) {
        int row = i >> 6, col = i & 63;
        float v = ssp(sC[row * LDC + col] + __ldg(&b1[col]));
        sA[row * LDA + col] = __float2half_rn(v);
    }
    load_B(sB, W2, tid);
    __syncthreads();
    wmma_gemm(sA, sB, sC);
    __syncthreads();

    for (int i = tid; i < 128 * 64; i += 256) {
        int row = i >> 6, col = i & 63;
        size_t gr = r0 + row;
        float v = 0.0f;
        if (gr < N_ATOMS) {
            v = g_h[gr * HID + col] + sC[row * LDC + col] + __ldg(&b2[col]);
            g_h[gr * HID + col] = v;
        }
        sA[row * LDA + col] = __float2half_rn(v);
    }
    if (!fuse_next) return;

    load_B(sB, W3, tid);
    __syncthreads();
    wmma_gemm(sA, sB, sC);
    __syncthreads();
    for (int i = tid; i < 128 * 32; i += 256) {
        int row = i >> 5, c2 = i & 31;
        size_t gr = r0 + row;
        if (gr < N_ATOMS) {
            __half2 hv = __floats2half2_rn(sC[row * LDC + c2 * 2], sC[row * LDC + c2 * 2 + 1]);
            *(__half2*)(g_x + gr * HID + c2 * 2) = hv;
        }
    }
}

/* --------------- readout: per-atom MLP (64->32->1) + molecule sum -------- */
__global__ void readout_kernel(const int* __restrict__ batch,
                               const float* __restrict__ w1, const float* __restrict__ b1,
                               const float* __restrict__ w2, const float* __restrict__ b2) {
    int warp = (blockIdx.x * blockDim.x + threadIdx.x) >> 5;
    int lane = threadIdx.x & 31;
    if (warp >= N_ATOMS) return;

    float h0 = g_h[(size_t)warp * HID + lane];
    float h1 = g_h[(size_t)warp * HID + 32 + lane];

    float acc = b1[lane];
#pragma unroll
    for (int k = 0; k < 32; k++) {
        float hk = __shfl_sync(0xffffffffu, h0, k);
        acc = fmaf(hk, w1[k * 32 + lane], acc);
    }
#pragma unroll
    for (int k = 0; k < 32; k++) {
        float hk = __shfl_sync(0xffffffffu, h1, k);
        acc = fmaf(hk, w1[(32 + k) * 32 + lane], acc);
    }
    float t = ssp(acc) * w2[lane];
#pragma unroll
    for (int o = 16; o > 0; o >>= 1) t += __shfl_xor_sync(0xffffffffu, t, o);
    if (lane == 0) atomicAdd(&g_molsum[batch[warp]], t + b2[0]);
}

/* ------- out[g] = molsum[g]*fin_w + fin_b ; self-restore molsum ---------- */
__global__ void final_kernel(const float* __restrict__ fw, const float* __restrict__ fb,
                             float* __restrict__ out) {
    int g = blockIdx.x * blockDim.x + threadIdx.x;
    if (g < N_MOL) {
        float v = g_molsum[g];
        out[g] = v * fw[0] + fb[0];
        g_molsum[g] = 0.0f;
    }
}

/* ========================================================================= */
extern "C" void kernel_launch(void* const* d_in, const int* in_sizes, int n_in,
                              void* d_out, int out_size) {
    const int*   z      = (const int*)d_in[0];
    const float* pos    = (const float*)d_in[1];
    const int*   batch  = (const int*)d_in[2];
    const int*   ei     = (const int*)d_in[3];
    const float* emb    = (const float*)d_in[4];
    const float* out_w1 = (const float*)d_in[5];
    const float* out_b1 = (const float*)d_in[6];
    const float* out_w2 = (const float*)d_in[7];
    const float* out_b2 = (const float*)d_in[8];
    const float* fin_w  = (const float*)d_in[9];
    const float* fin_b  = (const float*)d_in[10];
    const float* mlp_w1 = (const float*)d_in[11];
    const float* mlp_b1 = (const float*)d_in[12];
    const float* mlp_w2 = (const float*)d_in[13];
    const float* mlp_b2 = (const float*)d_in[14];
    const float* cf1    = (const float*)d_in[15];
    const float* cf2    = (const float*)d_in[16];
    const float* cf2b   = (const float*)d_in[17];
    const float* intw   = (const float*)d_in[18];
    const float* intb   = (const float*)d_in[19];

    (void)in_sizes; (void)n_in; (void)out_size;

    cudaFuncSetAttribute(aggregate_kernel,
                         cudaFuncAttributeMaxDynamicSharedMemorySize, TBL2_BYTES);
    cudaFuncSetAttribute(k2_scan_pack_densex,
                         cudaFuncAttributeMaxDynamicSharedMemorySize, SM_TOTAL);
    cudaFuncSetAttribute(dense_post_w,
                         cudaFuncAttributeMaxDynamicSharedMemorySize, SM_TOTAL);

    k1_prep_table_hist<<<WPREP_BLK + POS_BLK + TBL_BLK + HIST_BLK, 256>>>(
        cf1, cf2, intw, mlp_w1, mlp_b1, mlp_w2, mlp_b2, ei, pos);
    k2_scan_pack_densex<<<SCAN_BLK + PACK_BLK + DX_BLK + SCANC_BLK, 256, SM_TOTAL>>>(z, emb);
    scatter_kernel<<<(N_EDGES + 255) / 256, 256>>>(ei);

    for (int l = 0; l < NLAYERS; l++) {
        aggregate_kernel<<<AGG_BLOCKS, 1024, TBL2_BYTES>>>(l);
        dense_post_w<<<DX_BLK, 256, SM_TOTAL>>>(l, (l + 1 < NLAYERS),
                                                cf2b + (size_t)l * HID,
                                                intb + (size_t)l * HID);
    }

    int warp_blocks = (N_ATOMS * 32 + 255) / 256;
    readout_kernel<<<warp_blocks, 256>>>(batch, out_w1, out_b1, out_w2, out_b2);
    final_kernel<<<(N_MOL + 255) / 256, 256>>>(fin_w, fin_b, (float*)d_out);
}

// round 16
// speedup vs baseline: 1.2886x; 1.1819x over previous
#include <cuda_runtime.h>
#include <cuda_fp16.h>
#include <mma.h>
#include <math.h>

using namespace nvcuda;

#define N_ATOMS 100000
#define N_EDGES 3200000
#define N_MOL   2000
#define HID     64
#define NGAUSS  50
#define NLAYERS 3
#define TBL_T   512
#define TBL2_BYTES (TBL_T * HID * 4)       /* 128 KB: (a, delta/64) interleaved */
#define DMAX    8.6603f                    /* >= 5*sqrt(3) */
#define TBL_SCALE ((float)(TBL_T-1) / DMAX)
#define TBL_SCALE64 (TBL_SCALE * 64.0f)
#define TI6_MAX ((TBL_T - 2) * 64 + 63)    /* 32703 */
#define LOG2F_  0.69314718055994530942f
#define PI_OVER_CUTOFF 0.31415926535897932385f
#define SCAN_BLK 98
#define AGG_BLOCKS 148
#define TB_TPB  16

#define WPREP_BLK 48
#define POS_BLK   ((N_ATOMS + 255) / 256)
#define TBL_BLK   (NLAYERS * (TBL_T / TB_TPB))
#define HIST_BLK  ((N_EDGES + 255) / 256)

#define PACK_BLK  ((NLAYERS * TBL_T * 32 + 255) / 256)
#define DX_BLK    ((N_ATOMS + 127) / 128)
#define SCANC_BLK ((N_ATOMS + 255) / 256)

#define LDA 72
#define LDC 68
#define SM_A_OFF  0
#define SM_B_OFF  (128 * LDA * 2)
#define SM_C_OFF  (SM_B_OFF + 64 * LDA * 2)
#define SM_TOTAL  (SM_C_OFF + 128 * LDC * 4)

/* ------------------------- scratch (no allocs allowed) ------------------ */
__device__ int                g_hist[N_ATOMS];
__device__ int                g_row[N_ATOMS + 1];
__device__ int                g_cur[N_ATOMS];
__device__ int                g_part[128];
__device__ int                g_done;
__device__ int                g_flag;
__device__ unsigned int       g_edata[N_EDGES];      /* s:17 | ti:9 | f6:6 */
__device__ float4             g_pos4[N_ATOMS];
__device__ __align__(16)  __half g_traw[NLAYERS * TBL_T * HID];
__device__ __align__(16)  __half g_tbl2[NLAYERS * TBL_T * HID * 2];
__device__ __align__(128) __half g_h[(size_t)N_ATOMS * HID];     /* fp16 now */
__device__ __align__(128) __half g_x[(size_t)N_ATOMS * HID];
__device__ __align__(128) __half g_aggh[(size_t)N_ATOMS * HID];
__device__ float              g_molsum[N_MOL];
__device__ __align__(16) __half g_cf1h[NLAYERS * HID * HID];
__device__ __align__(16) __half g_cf2h[NLAYERS * HID * HID];
__device__ __align__(16) __half g_inth[NLAYERS * HID * HID];

__device__ __forceinline__ float ssp(float v) {
    return fmaxf(v, 0.0f) + log1pf(expf(-fabsf(v))) - LOG2F_;
}

/* --------------- wmma 128x64x64 tile helpers ----------------------------- */
__device__ __forceinline__ void wmma_gemm(const __half* sA, const __half* sB, float* sC) {
    int w = threadIdx.x >> 5;
    wmma::fragment<wmma::accumulator, 16, 16, 16, float> c[4];
#pragma unroll
    for (int n = 0; n < 4; n++) wmma::fill_fragment(c[n], 0.0f);
#pragma unroll
    for (int k = 0; k < 4; k++) {
        wmma::fragment<wmma::matrix_a, 16, 16, 16, __half, wmma::row_major> a;
        wmma::load_matrix_sync(a, sA + (w * 16) * LDA + k * 16, LDA);
#pragma unroll
        for (int n = 0; n < 4; n++) {
            wmma::fragment<wmma::matrix_b, 16, 16, 16, __half, wmma::row_major> b;
            wmma::load_matrix_sync(b, sB + (k * 16) * LDA + n * 16, LDA);
            wmma::mma_sync(c[n], a, b, c[n]);
        }
    }
#pragma unroll
    for (int n = 0; n < 4; n++)
        wmma::store_matrix_sync(sC + (w * 16) * LDC + n * 16, c[n], LDC, wmma::mem_row_major);
}

/* 128x32x64 variant for the readout GEMM */
__device__ __forceinline__ void wmma_gemm32(const __half* sA, const __half* sB, float* sC) {
    int w = threadIdx.x >> 5;
    wmma::fragment<wmma::accumulator, 16, 16, 16, float> c[2];
#pragma unroll
    for (int n = 0; n < 2; n++) wmma::fill_fragment(c[n], 0.0f);
#pragma unroll
    for (int k = 0; k < 4; k++) {
        wmma::fragment<wmma::matrix_a, 16, 16, 16, __half, wmma::row_major> a;
        wmma::load_matrix_sync(a, sA + (w * 16) * LDA + k * 16, LDA);
#pragma unroll
        for (int n = 0; n < 2; n++) {
            wmma::fragment<wmma::matrix_b, 16, 16, 16, __half, wmma::row_major> b;
            wmma::load_matrix_sync(b, sB + (k * 16) * LDA + n * 16, LDA);
            wmma::mma_sync(c[n], a, b, c[n]);
        }
    }
#pragma unroll
    for (int n = 0; n < 2; n++)
        wmma::store_matrix_sync(sC + (w * 16) * LDC + n * 16, c[n], LDC, wmma::mem_row_major);
}

__device__ __forceinline__ void load_B(__half* sB, const __half* W, int tid) {
    for (int i = tid; i < 64 * 32; i += 256) {
        int row = i >> 5, c2 = i & 31;
        *(unsigned int*)&sB[row * LDA + c2 * 2] = ((const unsigned int*)W)[row * 32 + c2];
    }
}

/* =========== K1: wprep + pos4 repack + table + hist (fused) ============== */
__global__ void __launch_bounds__(256) k1_prep_table_hist(
        const float* __restrict__ cf1, const float* __restrict__ cf2,
        const float* __restrict__ intw,
        const float* __restrict__ w1, const float* __restrict__ b1,
        const float* __restrict__ w2, const float* __restrict__ b2,
        const int* __restrict__ ei, const float* __restrict__ pos) {
    int bid = blockIdx.x;
    int tid = threadIdx.x;

    if (bid < WPREP_BLK) {
        int i = bid * 256 + tid;
        if (i < NLAYERS * HID * HID) {
            g_cf1h[i] = __float2half_rn(cf1[i]);
            g_cf2h[i] = __float2half_rn(cf2[i]);
            g_inth[i] = __float2half_rn(intw[i]);
        }
        return;
    }
    if (bid < WPREP_BLK + POS_BLK) {
        int i = (bid - WPREP_BLK) * 256 + tid;
        if (i < N_ATOMS)
            g_pos4[i] = make_float4(pos[3 * i], pos[3 * i + 1], pos[3 * i + 2], 0.0f);
        return;
    }
    if (bid < WPREP_BLK + POS_BLK + TBL_BLK) {
        __shared__ float W1s[NGAUSS][HID];
        __shared__ float W2s[HID][HID];
        __shared__ float rbfs[TB_TPB][NGAUSS];
        __shared__ float tmps[TB_TPB][HID];
        int tb = bid - WPREP_BLK - POS_BLK;
        int l = tb / (TBL_T / TB_TPB);
        int tbase = (tb % (TBL_T / TB_TPB)) * TB_TPB;

        for (int i = tid; i < NGAUSS * HID; i += 256)
            W1s[i / HID][i % HID] = w1[(size_t)l * NGAUSS * HID + i];
        for (int i = tid; i < HID * HID; i += 256)
            W2s[i >> 6][i & 63] = w2[(size_t)l * HID * HID + i];
        for (int i = tid; i < TB_TPB * NGAUSS; i += 256) {
            int tt = i / NGAUSS, k = i % NGAUSS;
            float d = (float)(tbase + tt) * (DMAX / (float)(TBL_T - 1));
            float off = (float)k * (10.0f / 49.0f);
            float u = d - off;
            const float coeff = -0.5f * (49.0f / 10.0f) * (49.0f / 10.0f);
            rbfs[tt][k] = expf(coeff * u * u);
        }
        __syncthreads();

        for (int i = tid; i < TB_TPB * HID; i += 256) {
            int tt = i >> 6, j = i & 63;
            float acc = b1[l * HID + j];
#pragma unroll
            for (int k = 0; k < NGAUSS; k++) acc = fmaf(rbfs[tt][k], W1s[k][j], acc);
            tmps[tt][j] = ssp(acc);
        }
        __syncthreads();

        for (int i = tid; i < TB_TPB * HID; i += 256) {
            int tt = i >> 6, j = i & 63;
            float acc = b2[l * HID + j];
#pragma unroll
            for (int k = 0; k < HID; k++) acc = fmaf(tmps[tt][k], W2s[k][j], acc);
            float d = (float)(tbase + tt) * (DMAX / (float)(TBL_T - 1));
            float C = 0.5f * (cosf(d * PI_OVER_CUTOFF) + 1.0f);
            g_traw[((size_t)l * TBL_T + tbase + tt) * HID + j] = __float2half_rn(acc * C);
        }
        return;
    }
    int e = (bid - WPREP_BLK - POS_BLK - TBL_BLK) * 256 + tid;
    if (e < N_EDGES) atomicAdd(&g_hist[ei[N_EDGES + e]], 1);
}

/* ====== K2: scanA(+B last block) + pack + dense_x + scanC(spin) ========== */
__global__ void __launch_bounds__(256) k2_scan_pack_densex(const int* __restrict__ z,
                                                           const float* __restrict__ emb) {
    int bid = blockIdx.x;
    int tid = threadIdx.x;

    if (bid < SCAN_BLK) {
        __shared__ int wsum[8];
        __shared__ int s_last;
        int lane = tid & 31, wid = tid >> 5;
        int idx = bid * 1024 + tid * 4;

        int v0 = (idx + 0 < N_ATOMS) ? g_hist[idx + 0] : 0;
        int v1 = (idx + 1 < N_ATOMS) ? g_hist[idx + 1] : 0;
        int v2 = (idx + 2 < N_ATOMS) ? g_hist[idx + 2] : 0;
        int v3 = (idx + 3 < N_ATOMS) ? g_hist[idx + 3] : 0;
        if (idx + 0 < N_ATOMS) g_hist[idx + 0] = 0;
        if (idx + 1 < N_ATOMS) g_hist[idx + 1] = 0;
        if (idx + 2 < N_ATOMS) g_hist[idx + 2] = 0;
        if (idx + 3 < N_ATOMS) g_hist[idx + 3] = 0;

        int s = v0 + v1 + v2 + v3;
        int si = s;
#pragma unroll
        for (int o = 1; o < 32; o <<= 1) {
            int u = __shfl_up_sync(0xffffffffu, si, o);
            if (lane >= o) si += u;
        }
        if (lane == 31) wsum[wid] = si;
        __syncthreads();
        if (wid == 0 && lane < 8) {
            int w = wsum[lane];
#pragma unroll
            for (int o = 1; o < 8; o <<= 1) {
                int u = __shfl_up_sync(0x000000ffu, w, o);
                if (lane >= o) w += u;
            }
            wsum[lane] = w;
        }
        __syncthreads();
        int off = ((wid > 0) ? wsum[wid - 1] : 0) + (si - s);
        if (idx + 0 < N_ATOMS) g_row[idx + 0] = off;
        if (idx + 1 < N_ATOMS) g_row[idx + 1] = off + v0;
        if (idx + 2 < N_ATOMS) g_row[idx + 2] = off + v0 + v1;
        if (idx + 3 < N_ATOMS) g_row[idx + 3] = off + v0 + v1 + v2;
        if (tid == 0) g_part[bid] = wsum[7];

        __threadfence();
        if (tid == 0) s_last = (atomicAdd(&g_done, 1) == SCAN_BLK - 1);
        __syncthreads();
        if (s_last) {
            __threadfence();
            if (tid < 32) {
                int lane2 = tid;
                int i = lane2 * 4;
                int u0 = (i + 0 < SCAN_BLK) ? g_part[i + 0] : 0;
                int u1 = (i + 1 < SCAN_BLK) ? g_part[i + 1] : 0;
                int u2 = (i + 2 < SCAN_BLK) ? g_part[i + 2] : 0;
                int u3 = (i + 3 < SCAN_BLK) ? g_part[i + 3] : 0;
                int ss = u0 + u1 + u2 + u3;
                int ssi = ss;
#pragma unroll
                for (int o = 1; o < 32; o <<= 1) {
                    int u = __shfl_up_sync(0xffffffffu, ssi, o);
                    if (lane2 >= o) ssi += u;
                }
                int excl = ssi - ss;
                if (i + 0 < SCAN_BLK) g_part[i + 0] = excl;
                if (i + 1 < SCAN_BLK) g_part[i + 1] = excl + u0;
                if (i + 2 < SCAN_BLK) g_part[i + 2] = excl + u0 + u1;
                if (i + 3 < SCAN_BLK) g_part[i + 3] = excl + u0 + u1 + u2;
                if (lane2 == 31) g_row[N_ATOMS] = ssi;
                __syncwarp();
                if (lane2 == 0) {
                    g_done = 0;
                    __threadfence();
                    g_flag = 1;
                }
            }
        }
        return;
    }
    if (bid < SCAN_BLK + PACK_BLK) {
        int i = (bid - SCAN_BLK) * 256 + tid;
        if (i >= NLAYERS * TBL_T * 32) return;
        int c2 = i & 31;
        int t  = (i >> 5) & (TBL_T - 1);
        int l  = i / (TBL_T * 32);
        const __half2* raw = (const __half2*)g_traw;
        __half2 a = raw[((size_t)l * TBL_T + t) * 32 + c2];
        int tn = (t + 1 < TBL_T) ? t + 1 : t;
        __half2 b = raw[((size_t)l * TBL_T + tn) * 32 + c2];
        __half2 d = __hmul2(__hsub2(b, a), __float2half2_rn(1.0f / 64.0f));
        __half2* dst = (__half2*)g_tbl2;
        dst[(((size_t)l * TBL_T + t) * 32 + c2) * 2 + 0] = a;
        dst[(((size_t)l * TBL_T + t) * 32 + c2) * 2 + 1] = d;
        return;
    }
    if (bid < SCAN_BLK + PACK_BLK + DX_BLK) {
        extern __shared__ char sm[];
        __half* sA = (__half*)(sm + SM_A_OFF);
        __half* sB = (__half*)(sm + SM_B_OFF);
        float*  sC = (float*)(sm + SM_C_OFF);
        size_t r0 = (size_t)(bid - SCAN_BLK - PACK_BLK) * 128;

        for (int i = tid; i < 128 * 64; i += 256) {
            int row = i >> 6, col = i & 63;
            size_t gr = r0 + row;
            float v = 0.0f;
            __half hv = __ushort_as_half(0);
            if (gr < N_ATOMS) {
                v = emb[(size_t)z[gr] * HID + col];
                hv = __float2half_rn(v);
                g_h[gr * HID + col] = hv;
            }
            sA[row * LDA + col] = hv;
        }
        load_B(sB, g_cf1h, tid);
        __syncthreads();
        wmma_gemm(sA, sB, sC);
        __syncthreads();
        for (int i = tid; i < 128 * 32; i += 256) {
            int row = i >> 5, c2 = i & 31;
            size_t gr = r0 + row;
            if (gr < N_ATOMS) {
                __half2 hv = __floats2half2_rn(sC[row * LDC + c2 * 2], sC[row * LDC + c2 * 2 + 1]);
                *(__half2*)(g_x + gr * HID + c2 * 2) = hv;
            }
        }
        return;
    }
    if (tid == 0) {
        while (!*((volatile int*)&g_flag)) __nanosleep(64);
    }
    __syncthreads();
    __threadfence();
    int i = (bid - SCAN_BLK - PACK_BLK - DX_BLK) * 256 + tid;
    if (i >= N_ATOMS) return;
    int v = g_row[i] + g_part[i >> 10];
    g_row[i] = v;
    g_cur[i] = v;
}

/* =================== K3: scatter (32-bit records, 6-bit f) =============== */
__global__ void scatter_kernel(const int* __restrict__ ei) {
    int e = blockIdx.x * blockDim.x + threadIdx.x;
    if (e == 0) g_flag = 0;
    if (e >= N_EDGES) return;
    int s = ei[e];
    int t = ei[N_EDGES + e];
    float4 ps = g_pos4[s];
    float4 pt = g_pos4[t];
    float dx = ps.x - pt.x, dy = ps.y - pt.y, dz = ps.z - pt.z;
    float d = sqrtf(dx * dx + dy * dy + dz * dz);
    unsigned ti6 = min((unsigned)(d * TBL_SCALE64), (unsigned)TI6_MAX);
    int p = atomicAdd(&g_cur[t], 1);
    g_edata[p] = ((unsigned)s << 15) | ti6;
}

/* ====== K4: aggregate — half-warp/node, 8-edge flush (PROFILED) ========== */
__global__ void __launch_bounds__(1024, 1) aggregate_kernel(int layer) {
    extern __shared__ __align__(16) char s_raw[];
    {
        const uint4* src = (const uint4*)(g_tbl2 + (size_t)layer * TBL_T * HID * 2);
        uint4* dst = (uint4*)s_raw;
        for (int i = threadIdx.x; i < TBL2_BYTES / 16; i += 1024) dst[i] = src[i];
    }
    __syncthreads();

    int lane = threadIdx.x & 31;
    int wib  = threadIdx.x >> 5;
    int half = lane >> 4;
    int l16  = lane & 15;
    unsigned lds_off = (unsigned)l16 << 4;
    const char* xbase = (const char*)g_x + (l16 << 3);

    for (int nodeb = blockIdx.x * 64 + wib * 2; nodeb < N_ATOMS; nodeb += gridDim.x * 64) {
        int node = nodeb + half;
        int beg = 0, end = 0;
        if (node < N_ATOMS) { beg = g_row[node]; end = g_row[node + 1]; }

        int nb = (end - beg + 15) >> 4;
        int nbmax = max(nb, __shfl_xor_sync(0xffffffffu, nb, 16));

        float accf0 = 0.0f, accf1 = 0.0f, accf2 = 0.0f, accf3 = 0.0f;

        for (int b = 0; b < nbmax; b++) {
            int base = beg + (b << 4);
            int cnt = min(16, end - base);
            unsigned pk = (l16 < cnt) ? __ldcs(&g_edata[base + l16]) : 0u;
            int cmax = max(cnt, __shfl_xor_sync(0xffffffffu, cnt, 16));

            __half2 a0 = __half2half2(__ushort_as_half(0));
            __half2 a1 = a0;

#define EDGE(J) do {                                                          \
            unsigned p = __shfl_sync(0xffffffffu, pk, (J), 16);               \
            uint2 xv = make_uint2(0u, 0u);                                    \
            if ((J) < cnt)                                                    \
                xv = *(const uint2*)(xbase + ((size_t)(p >> 15) << 7));       \
            uint4 ad = *(const uint4*)(s_raw + ((p & 0x7FC0u) << 2) + lds_off); \
            __half2 f2 = __half2half2(__ushort2half_rn((unsigned short)(p & 63u))); \
            a0 = __hadd2(a0, __hmul2(__hfma2(f2, *(__half2*)&ad.y, *(__half2*)&ad.x), *(__half2*)&xv.x)); \
            a1 = __hadd2(a1, __hmul2(__hfma2(f2, *(__half2*)&ad.w, *(__half2*)&ad.z), *(__half2*)&xv.y)); \
        } while (0)

            int j = 0;
            for (; j + 8 <= cmax; j += 8) {
                EDGE(j + 0); EDGE(j + 1); EDGE(j + 2); EDGE(j + 3);
                EDGE(j + 4); EDGE(j + 5); EDGE(j + 6); EDGE(j + 7);
                float2 v0 = __half22float2(a0);
                float2 v1 = __half22float2(a1);
                accf0 += v0.x; accf1 += v0.y;
                accf2 += v1.x; accf3 += v1.y;
                a0 = __half2half2(__ushort_as_half(0));
                a1 = a0;
            }
            for (; j < cmax; j++) EDGE(j);
#undef EDGE
            float2 v0 = __half22float2(a0);
            float2 v1 = __half22float2(a1);
            accf0 += v0.x; accf1 += v0.y;
            accf2 += v1.x; accf3 += v1.y;
        }

        if (node < N_ATOMS) {
            __half2 h0 = __floats2half2_rn(accf0, accf1);
            __half2 h1 = __floats2half2_rn(accf2, accf3);
            uint2 st;
            st.x = *(unsigned*)&h0;
            st.y = *(unsigned*)&h1;
            *(uint2*)((char*)g_aggh + (size_t)node * 128 + (l16 << 3)) = st;
        }
    }
}

/* --- h += ssp(agg@W1+b1)@W2+b2 ; then x=h@W3 OR fused readout ------------ */
__global__ void __launch_bounds__(256) dense_post_w(int l, int fuse_next,
                                                    const float* __restrict__ b1,
                                                    const float* __restrict__ b2,
                                                    const int* __restrict__ batch,
                                                    const float* __restrict__ ow1,
                                                    const float* __restrict__ ob1,
                                                    const float* __restrict__ ow2,
                                                    const float* __restrict__ ob2) {
    extern __shared__ char sm[];
    __half* sA = (__half*)(sm + SM_A_OFF);
    __half* sB = (__half*)(sm + SM_B_OFF);
    float*  sC = (float*)(sm + SM_C_OFF);
    int tid = threadIdx.x;
    size_t r0 = (size_t)blockIdx.x * 128;

    const __half* W1 = g_cf2h + (size_t)l * HID * HID;
    const __half* W2 = g_inth + (size_t)l * HID * HID;
    const __half* W3 = g_cf1h + (size_t)(l + 1 < NLAYERS ? l + 1 : 0) * HID * HID;

    for (int i = tid; i < 128 * 32; i += 256) {
        int row = i >> 5, c2 = i & 31;
        unsigned int v = 0;
        if (r0 + row < N_ATOMS)
            v = ((const unsigned int*)g_aggh)[(r0 + row) * 32 + c2];
        *(unsigned int*)&sA[row * LDA + c2 * 2] = v;
    }
    load_B(sB, W1, tid);
    __syncthreads();
    wmma_gemm(sA, sB, sC);
    __syncthreads();

    for (int i = tid; i < 128 * 64; i += 256) {
        int row = i >> 6, col = i & 63;
        float v = ssp(sC[row * LDC + col] + __ldg(&b1[col]));
        sA[row * LDA + col] = __float2half_rn(v);
    }
    load_B(sB, W2, tid);
    __syncthreads();
    wmma_gemm(sA, sB, sC);
    __syncthreads();

    /* h(fp16) += C + b2 ; sA = h_new */
    for (int i = tid; i < 128 * 32; i += 256) {
        int row = i >> 5, c2 = i & 31;
        size_t gr = r0 + row;
        if (gr < N_ATOMS) {
            unsigned hraw = ((const unsigned*)g_h)[gr * 32 + c2];
            float2 hf = __half22float2(*(__half2*)&hraw);
            float v0 = hf.x + sC[row * LDC + c2 * 2]     + __ldg(&b2[c2 * 2]);
            float v1 = hf.y + sC[row * LDC + c2 * 2 + 1] + __ldg(&b2[c2 * 2 + 1]);
            __half2 nh = __floats2half2_rn(v0, v1);
            ((unsigned*)g_h)[gr * 32 + c2] = *(unsigned*)&nh;
            *(unsigned*)&sA[row * LDA + c2 * 2] = *(unsigned*)&nh;
        } else {
            *(unsigned*)&sA[row * LDA + c2 * 2] = 0u;
        }
    }

    if (fuse_next) {
        load_B(sB, W3, tid);
        __syncthreads();
        wmma_gemm(sA, sB, sC);
        __syncthreads();
        for (int i = tid; i < 128 * 32; i += 256) {
            int row = i >> 5, c2 = i & 31;
            size_t gr = r0 + row;
            if (gr < N_ATOMS) {
                __half2 hv = __floats2half2_rn(sC[row * LDC + c2 * 2], sC[row * LDC + c2 * 2 + 1]);
                *(__half2*)(g_x + gr * HID + c2 * 2) = hv;
            }
        }
        return;
    }

    /* fused readout: sC[128x32] = h_new @ out_w1 ; per-atom ssp dot w2 */
    for (int i = tid; i < 64 * 32; i += 256) {
        int row = i >> 5, col = i & 31;
        sB[row * LDA + col] = __float2half_rn(__ldg(&ow1[row * 32 + col]));
    }
    __syncthreads();
    wmma_gemm32(sA, sB, sC);
    __syncthreads();
    if (tid < 128) {
        size_t gr = r0 + tid;
        if (gr < N_ATOMS) {
            float acc = __ldg(&ob2[0]);
#pragma unroll
            for (int j = 0; j < 32; j++)
                acc += ssp(sC[tid * LDC + j] + __ldg(&ob1[j])) * __ldg(&ow2[j]);
            atomicAdd(&g_molsum[__ldg(&batch[gr])], acc);
        }
    }
}

/* ------- out[g] = molsum[g]*fin_w + fin_b ; self-restore molsum ---------- */
__global__ void final_kernel(const float* __restrict__ fw, const float* __restrict__ fb,
                             float* __restrict__ out) {
    int g = blockIdx.x * blockDim.x + threadIdx.x;
    if (g < N_MOL) {
        float v = g_molsum[g];
        out[g] = v * fw[0] + fb[0];
        g_molsum[g] = 0.0f;
    }
}

/* ========================================================================= */
extern "C" void kernel_launch(void* const* d_in, const int* in_sizes, int n_in,
                              void* d_out, int out_size) {
    const int*   z      = (const int*)d_in[0];
    const float* pos    = (const float*)d_in[1];
    const int*   batch  = (const int*)d_in[2];
    const int*   ei     = (const int*)d_in[3];
    const float* emb    = (const float*)d_in[4];
    const float* out_w1 = (const float*)d_in[5];
    const float* out_b1 = (const float*)d_in[6];
    const float* out_w2 = (const float*)d_in[7];
    const float* out_b2 = (const float*)d_in[8];
    const float* fin_w  = (const float*)d_in[9];
    const float* fin_b  = (const float*)d_in[10];
    const float* mlp_w1 = (const float*)d_in[11];
    const float* mlp_b1 = (const float*)d_in[12];
    const float* mlp_w2 = (const float*)d_in[13];
    const float* mlp_b2 = (const float*)d_in[14];
    const float* cf1    = (const float*)d_in[15];
    const float* cf2    = (const float*)d_in[16];
    const float* cf2b   = (const float*)d_in[17];
    const float* intw   = (const float*)d_in[18];
    const float* intb   = (const float*)d_in[19];

    (void)in_sizes; (void)n_in; (void)out_size;

    cudaFuncSetAttribute(aggregate_kernel,
                         cudaFuncAttributeMaxDynamicSharedMemorySize, TBL2_BYTES);
    cudaFuncSetAttribute(k2_scan_pack_densex,
                         cudaFuncAttributeMaxDynamicSharedMemorySize, SM_TOTAL);
    cudaFuncSetAttribute(dense_post_w,
                         cudaFuncAttributeMaxDynamicSharedMemorySize, SM_TOTAL);

    k1_prep_table_hist<<<WPREP_BLK + POS_BLK + TBL_BLK + HIST_BLK, 256>>>(
        cf1, cf2, intw, mlp_w1, mlp_b1, mlp_w2, mlp_b2, ei, pos);
    k2_scan_pack_densex<<<SCAN_BLK + PACK_BLK + DX_BLK + SCANC_BLK, 256, SM_TOTAL>>>(z, emb);
    scatter_kernel<<<(N_EDGES + 255) / 256, 256>>>(ei);

    for (int l = 0; l < NLAYERS; l++) {
        aggregate_kernel<<<AGG_BLOCKS, 1024, TBL2_BYTES>>>(l);
        dense_post_w<<<DX_BLK, 256, SM_TOTAL>>>(l, (l + 1 < NLAYERS),
                                                cf2b + (size_t)l * HID,
                                                intb + (size_t)l * HID,
                                                batch, out_w1, out_b1, out_w2, out_b2);
    }

    final_kernel<<<(N_MOL + 255) / 256, 256>>>(fin_w, fin_b, (float*)d_out);
}